// round 13
// baseline (speedup 1.0000x reference)
#include <cuda_runtime.h>
#include <cuda_fp16.h>
#include <mma.h>
#include <math.h>
#include <stdint.h>

using namespace nvcuda;

#define N_TOK 4096
#define D_DIM 2048
#define F_DIM 8192
#define E_EXP 8
#define R_RANK 8
#define SCALING 2.0f

#define BM 128
#define BN 128
#define BK 16
#define TM 8
#define TN 8

// ---------------- scratch (~420MB total; R8 ran fine at ~512MB) --------------
__device__ __half x16h[(size_t)N_TOK * D_DIM];
__device__ __half x16l[(size_t)N_TOK * D_DIM];
__device__ __half w1h16[(size_t)F_DIM * D_DIM];
__device__ __half w1l16[(size_t)F_DIM * D_DIM];
__device__ __half w2h16[(size_t)D_DIM * F_DIM];
__device__ __half w2l16[(size_t)D_DIM * F_DIM];
__device__ __half g16h[(size_t)N_TOK * F_DIM];
__device__ __half g16l[(size_t)N_TOK * F_DIM];
__device__ __half h16a[(size_t)N_TOK * F_DIM];
__device__ __half h16b[(size_t)N_TOK * F_DIM];
__device__ float z1c[N_TOK * 16];
__device__ float z2s[N_TOK * 16];
__device__ int   eidx[N_TOK * 2];
__device__ float ew[N_TOK * 2];
__device__ float wsum_buf[N_TOK];
__device__ int gf1, gf2;

__device__ __forceinline__ float gelu_new(float x) {
    float x3 = x * x * x;
    float t = tanhf(0.7978845608028654f * (x + 0.044715f * x3));
    return 0.5f * x * (1.0f + t);
}

__global__ void reset_kernel(){ gf1 = 0; gf2 = 0; }

// ---------------- fp16 hi/lo split conversion --------------------------------
__global__ __launch_bounds__(256) void cvt16(
    const float* __restrict__ src, __half* __restrict__ hi, __half* __restrict__ lo,
    int cols)
{
    int row = blockIdx.x;
    const float4* s = (const float4*)(src + (size_t)row * cols);
    __half2* dh = (__half2*)(hi + (size_t)row * cols);
    __half2* dl = (__half2*)(lo + (size_t)row * cols);
    for (int i = threadIdx.x; i < cols / 4; i += 256){
        float4 v = s[i];
        __half hx = __float2half_rn(v.x), hy = __float2half_rn(v.y);
        __half hz = __float2half_rn(v.z), hw = __float2half_rn(v.w);
        dh[2*i]   = __halves2half2(hx, hy);
        dh[2*i+1] = __halves2half2(hz, hw);
        dl[2*i]   = __halves2half2(__float2half_rn(v.x - __half2float(hx)),
                                   __float2half_rn(v.y - __half2float(hy)));
        dl[2*i+1] = __halves2half2(__float2half_rn(v.z - __half2float(hz)),
                                   __float2half_rn(v.w - __half2float(hw)));
    }
}

// ---------------- router — verbatim R1 ---------------------------------------
__global__ __launch_bounds__(256) void router_kernel(
    const float* __restrict__ x, const float* __restrict__ Wr,
    const float* __restrict__ br, const float* __restrict__ A1)
{
    int n = blockIdx.x;
    int tid = threadIdx.x;
    __shared__ float xs[D_DIM];
    __shared__ float red[16][8];
    __shared__ int s_idx[2];

    for (int d = tid; d < D_DIM; d += 256) xs[d] = x[(size_t)n * D_DIM + d];
    __syncthreads();

    float acc[E_EXP];
#pragma unroll
    for (int e = 0; e < E_EXP; e++) acc[e] = 0.f;
    for (int d = tid; d < D_DIM; d += 256) {
        float xv = xs[d];
#pragma unroll
        for (int e = 0; e < E_EXP; e++) acc[e] += xv * Wr[e * D_DIM + d];
    }
#pragma unroll
    for (int e = 0; e < E_EXP; e++) {
        float v = acc[e];
        for (int o = 16; o > 0; o >>= 1) v += __shfl_down_sync(0xffffffffu, v, o);
        if ((tid & 31) == 0) red[e][tid >> 5] = v;
    }
    __syncthreads();

    if (tid == 0) {
        float lg[E_EXP];
#pragma unroll
        for (int e = 0; e < E_EXP; e++) {
            float v = 0.f;
#pragma unroll
            for (int w = 0; w < 8; w++) v += red[e][w];
            lg[e] = v + br[e];
        }
        float mx = lg[0];
#pragma unroll
        for (int e = 1; e < E_EXP; e++) mx = fmaxf(mx, lg[e]);
        float p[E_EXP], se = 0.f;
#pragma unroll
        for (int e = 0; e < E_EXP; e++) { p[e] = expf(lg[e] - mx); se += p[e]; }
        float inv = 1.0f / se;
#pragma unroll
        for (int e = 0; e < E_EXP; e++) p[e] *= inv;
        int i0 = 0;
#pragma unroll
        for (int e = 1; e < E_EXP; e++) if (p[e] > p[i0]) i0 = e;
        int i1 = -1;
#pragma unroll
        for (int e = 0; e < E_EXP; e++) {
            if (e == i0) continue;
            if (i1 < 0 || p[e] > p[i1]) i1 = e;
        }
        s_idx[0] = i0; s_idx[1] = i1;
        eidx[2 * n] = i0; eidx[2 * n + 1] = i1;
        ew[2 * n] = p[i0]; ew[2 * n + 1] = p[i1];
        wsum_buf[n] = p[i0] + p[i1];
    }
    __syncthreads();

    int e0 = s_idx[0], e1 = s_idx[1];
    float u[16];
#pragma unroll
    for (int i = 0; i < 16; i++) u[i] = 0.f;
    for (int d = tid; d < D_DIM; d += 256) {
        float xv = xs[d];
#pragma unroll
        for (int r = 0; r < R_RANK; r++) {
            u[r]     += xv * A1[((size_t)e0 * R_RANK + r) * D_DIM + d];
            u[8 + r] += xv * A1[((size_t)e1 * R_RANK + r) * D_DIM + d];
        }
    }
    __syncthreads();
#pragma unroll
    for (int i = 0; i < 16; i++) {
        float v = u[i];
        for (int o = 16; o > 0; o >>= 1) v += __shfl_down_sync(0xffffffffu, v, o);
        if ((tid & 31) == 0) red[i][tid >> 5] = v;
    }
    __syncthreads();
    if (tid < 16) {
        float v = 0.f;
#pragma unroll
        for (int w = 0; w < 8; w++) v += red[tid][w];
        z1c[n * 16 + tid] = v * SCALING;
    }
}

// ============================================================================
// fp16 x3 fused GEMM. Pre-split operands; 48KB static smem:
// 2 stages x [Ah|Al|Bh|Bl], each tile 128 rows x 24-half stride (16 used).
// ============================================================================
typedef wmma::fragment<wmma::matrix_a, 16,16,16, __half, wmma::row_major> HA;
typedef wmma::fragment<wmma::matrix_b, 16,16,16, __half, wmma::col_major> HB;
typedef wmma::fragment<wmma::accumulator, 16,16,16, float> HC;

#define TSTRIDE 24
#define TSIZE   (128 * TSTRIDE)      // 3072 halves per tile
#define STAGE   (4 * TSIZE)          // 12288 halves per stage

__device__ __forceinline__ void gemm16(
    HC (&acc)[2][4],
    const __half* Ah, const __half* Al,
    const __half* Bh, const __half* Bl,
    int K, __half* sm)
{
    const int tid = threadIdx.x, wid = tid >> 5;
    const int wr = wid & 3, wc = wid >> 2;
    const int row = tid >> 1, hf = (tid & 1) * 8;
#pragma unroll
    for (int i = 0; i < 2; i++)
#pragma unroll
    for (int j = 0; j < 4; j++) wmma::fill_fragment(acc[i][j], 0.f);

    uint4 ra, rl, rb, rbl;
    size_t go = (size_t)row * K + hf;
    ra  = *(const uint4*)(Ah + go);
    rl  = *(const uint4*)(Al + go);
    rb  = *(const uint4*)(Bh + go);
    rbl = *(const uint4*)(Bl + go);
    {
        int so = row * TSTRIDE + hf;
        *(uint4*)(sm + so) = ra;
        *(uint4*)(sm + TSIZE + so) = rl;
        *(uint4*)(sm + 2*TSIZE + so) = rb;
        *(uint4*)(sm + 3*TSIZE + so) = rbl;
    }
    __syncthreads();

    const int nch = K / 16;
    for (int c = 0; c < nch; c++){
        if (c + 1 < nch){
            size_t g2 = (size_t)row * K + (c + 1) * 16 + hf;
            ra  = *(const uint4*)(Ah + g2);
            rl  = *(const uint4*)(Al + g2);
            rb  = *(const uint4*)(Bh + g2);
            rbl = *(const uint4*)(Bl + g2);
        }
        const __half* st = sm + (c & 1) * STAGE;
        HA ah[2], al[2];
#pragma unroll
        for (int i = 0; i < 2; i++){
            wmma::load_matrix_sync(ah[i], st + (wr*32 + i*16)*TSTRIDE, TSTRIDE);
            wmma::load_matrix_sync(al[i], st + TSIZE + (wr*32 + i*16)*TSTRIDE, TSTRIDE);
        }
#pragma unroll
        for (int j = 0; j < 4; j++){
            HB bh, bl;
            wmma::load_matrix_sync(bh, st + 2*TSIZE + (wc*64 + j*16)*TSTRIDE, TSTRIDE);
            wmma::load_matrix_sync(bl, st + 3*TSIZE + (wc*64 + j*16)*TSTRIDE, TSTRIDE);
#pragma unroll
            for (int i = 0; i < 2; i++){
                wmma::mma_sync(acc[i][j], ah[i], bh, acc[i][j]);
                wmma::mma_sync(acc[i][j], ah[i], bl, acc[i][j]);
                wmma::mma_sync(acc[i][j], al[i], bh, acc[i][j]);
            }
        }
        if (c + 1 < nch){
            __half* d = sm + ((c + 1) & 1) * STAGE;
            int so = row * TSTRIDE + hf;
            *(uint4*)(d + so) = ra;
            *(uint4*)(d + TSIZE + so) = rl;
            *(uint4*)(d + 2*TSIZE + so) = rb;
            *(uint4*)(d + 3*TSIZE + so) = rbl;
        }
        __syncthreads();
    }
}

// ============================================================================
// fc1 fp16: x @ W1^T -> +b1, LoRA1, gelu -> h16 planes, g16 hi/lo
// ============================================================================
__global__ __launch_bounds__(256) void fc1_f16(
    const float* __restrict__ b1, const float* __restrict__ B1)
{
    __shared__ __align__(16) __half smbuf[2 * STAGE];   // 49152 B
    int bn = blockIdx.x, bm = blockIdx.y;
    int tid = threadIdx.x, wid = tid >> 5, wr = wid & 3, wc = wid >> 2;
    HC acc[2][4];

    gemm16(acc,
        x16h + (size_t)bm*128*D_DIM, x16l + (size_t)bm*128*D_DIM,
        w1h16 + (size_t)bn*128*D_DIM, w1l16 + (size_t)bn*128*D_DIM,
        D_DIM, smbuf);

    float* Cs = (float*)smbuf;   // 64 x 136 floats = 34816 B
    for (int r = 0; r < 2; r++){
        __syncthreads();
        if ((wr >> 1) == r){
            int rl = (wr & 1) * 32;
#pragma unroll
            for (int i = 0; i < 2; i++)
#pragma unroll
            for (int j = 0; j < 4; j++)
                wmma::store_matrix_sync(Cs + (size_t)(rl+i*16)*136 + wc*64 + j*16,
                                        acc[i][j], 136, wmma::mem_row_major);
        }
        __syncthreads();

        int row_l = tid >> 2;
        int n = bm*128 + r*64 + row_l;
        int c0 = (tid & 3) * 32;
        int e0 = eidx[2*n], e1 = eidx[2*n+1];
        float w0 = ew[2*n], w1w = ew[2*n+1];
        float z0[8], z1[8];
#pragma unroll
        for (int q = 0; q < 8; q++){ z0[q] = z1c[n*16+q]; z1[q] = z1c[n*16+8+q]; }
        const float* crow = &Cs[(size_t)row_l*136];
        for (int jj = 0; jj < 32; jj += 2){
            int col = c0 + jj;
            int f = bn*128 + col;
            float ca = crow[col]   + b1[f];
            float cb = crow[col+1] + b1[f+1];
            const float4* q0 = (const float4*)&B1[((size_t)e0*F_DIM + f)*R_RANK];
            const float4* q1 = (const float4*)&B1[((size_t)e1*F_DIM + f)*R_RANK];
            float l0a=0.f, l0b=0.f, l1a=0.f, l1b=0.f;
#pragma unroll
            for (int q = 0; q < 2; q++){
                float4 u0=q0[q], u2=q0[2+q], v0=q1[q], v2=q1[2+q];
                l0a += z0[q*4+0]*u0.x + z0[q*4+1]*u0.y + z0[q*4+2]*u0.z + z0[q*4+3]*u0.w;
                l0b += z0[q*4+0]*u2.x + z0[q*4+1]*u2.y + z0[q*4+2]*u2.z + z0[q*4+3]*u2.w;
                l1a += z1[q*4+0]*v0.x + z1[q*4+1]*v0.y + z1[q*4+2]*v0.z + z1[q*4+3]*v0.w;
                l1b += z1[q*4+0]*v2.x + z1[q*4+1]*v2.y + z1[q*4+2]*v2.z + z1[q*4+3]*v2.w;
            }
            float h0a = gelu_new(ca + l0a), h0b_ = gelu_new(cb + l0b);
            float h1a = gelu_new(ca + l1a), h1b_ = gelu_new(cb + l1b);
            float g0 = w0*h0a + w1w*h1a, g1 = w0*h0b_ + w1w*h1b_;
            size_t off = (size_t)n*F_DIM + f;
            *(__half2*)&h16a[off] = __halves2half2(__float2half_rn(h0a), __float2half_rn(h0b_));
            *(__half2*)&h16b[off] = __halves2half2(__float2half_rn(h1a), __float2half_rn(h1b_));
            __half gh0 = __float2half_rn(g0), gh1 = __float2half_rn(g1);
            *(__half2*)&g16h[off] = __halves2half2(gh0, gh1);
            *(__half2*)&g16l[off] = __halves2half2(__float2half_rn(g0 - __half2float(gh0)),
                                                   __float2half_rn(g1 - __half2float(gh1)));
        }
    }
}

// ============================================================================
// fc2 fp16: g @ W2^T -> +ws*b2, LoRA2 -> out
// ============================================================================
__global__ __launch_bounds__(256) void fc2_f16(
    const float* __restrict__ b2, const float* __restrict__ B2,
    float* __restrict__ out)
{
    __shared__ __align__(16) __half smbuf[2 * STAGE];
    int bn = blockIdx.x, bm = blockIdx.y;
    int tid = threadIdx.x, wid = tid >> 5, wr = wid & 3, wc = wid >> 2;
    HC acc[2][4];

    gemm16(acc,
        g16h + (size_t)bm*128*F_DIM, g16l + (size_t)bm*128*F_DIM,
        w2h16 + (size_t)bn*128*F_DIM, w2l16 + (size_t)bn*128*F_DIM,
        F_DIM, smbuf);

    float* Cs = (float*)smbuf;
    for (int r = 0; r < 2; r++){
        __syncthreads();
        if ((wr >> 1) == r){
            int rl = (wr & 1) * 32;
#pragma unroll
            for (int i = 0; i < 2; i++)
#pragma unroll
            for (int j = 0; j < 4; j++)
                wmma::store_matrix_sync(Cs + (size_t)(rl+i*16)*136 + wc*64 + j*16,
                                        acc[i][j], 136, wmma::mem_row_major);
        }
        __syncthreads();

        int row_l = tid >> 2;
        int n = bm*128 + r*64 + row_l;
        int c0 = (tid & 3) * 32;
        float ws = wsum_buf[n];
        int e0 = eidx[2*n], e1 = eidx[2*n+1];
        float z0[8], z1[8];
#pragma unroll
        for (int q = 0; q < 8; q++){ z0[q] = z2s[n*16+q]; z1[q] = z2s[n*16+8+q]; }
        const float* crow = &Cs[(size_t)row_l*136];
        for (int jj = 0; jj < 32; jj++){
            int col = c0 + jj;
            int d = bn*128 + col;
            float c = crow[col] + ws*b2[d];
            const float4* q0 = (const float4*)&B2[((size_t)e0*D_DIM + d)*R_RANK];
            const float4* q1 = (const float4*)&B2[((size_t)e1*D_DIM + d)*R_RANK];
            float4 u0=q0[0], u1=q0[1], v0=q1[0], v1=q1[1];
            c += z0[0]*u0.x + z0[1]*u0.y + z0[2]*u0.z + z0[3]*u0.w
               + z0[4]*u1.x + z0[5]*u1.y + z0[6]*u1.z + z0[7]*u1.w;
            c += z1[0]*v0.x + z1[1]*v0.y + z1[2]*v0.z + z1[3]*v0.w
               + z1[4]*v1.x + z1[5]*v1.y + z1[6]*v1.z + z1[7]*v1.w;
            out[(size_t)n*D_DIM + d] = c;
        }
    }
}

// ============================================================================
// z2 — R1 structure, reads fp16 h planes
// ============================================================================
__global__ __launch_bounds__(256) void z2_kernel(const float* __restrict__ A2)
{
    int n = blockIdx.x;
    int k = blockIdx.y;
    int tid = threadIdx.x;
    int e = eidx[2 * n + k];
    const __half* h = (k ? h16b : h16a) + (size_t)n * F_DIM;
    const float* a2 = A2 + (size_t)e * R_RANK * F_DIM;

    float acc[R_RANK];
#pragma unroll
    for (int r = 0; r < R_RANK; r++) acc[r] = 0.f;

    for (int f = tid * 4; f < F_DIM; f += 1024) {
        uint2 hp = *(const uint2*)(h + f);
        __half2 p0 = *(__half2*)&hp.x, p1 = *(__half2*)&hp.y;
        float2 f0 = __half22float2(p0), f1 = __half22float2(p1);
#pragma unroll
        for (int r = 0; r < R_RANK; r++) {
            float4 av = *(const float4*)(a2 + (size_t)r * F_DIM + f);
            acc[r] += f0.x * av.x + f0.y * av.y + f1.x * av.z + f1.y * av.w;
        }
    }

    __shared__ float red[R_RANK][8];
#pragma unroll
    for (int r = 0; r < R_RANK; r++) {
        float v = acc[r];
        for (int o = 16; o > 0; o >>= 1) v += __shfl_down_sync(0xffffffffu, v, o);
        if ((tid & 31) == 0) red[r][tid >> 5] = v;
    }
    __syncthreads();
    if (tid < R_RANK) {
        float v = 0.f;
#pragma unroll
        for (int w = 0; w < 8; w++) v += red[tid][w];
        z2s[n * 16 + k * 8 + tid] = v * SCALING * ew[2 * n + k];
    }
}

// ============================================================================
// Verifiers + gated SIMT fallbacks
// ============================================================================
__global__ __launch_bounds__(256) void ver_fc1(
    const float* __restrict__ x, const float* __restrict__ W1,
    const float* __restrict__ b1, const float* __restrict__ B1)
{
    int s = blockIdx.x, tid = threadIdx.x;
    int n = (s * 97) & (N_TOK - 1);
    int f = (s * 53 + 7) & (F_DIM - 1);
    float p = 0.f;
    for (int d = tid; d < D_DIM; d += 256)
        p += x[(size_t)n*D_DIM + d] * W1[(size_t)f*D_DIM + d];
    for (int o = 16; o > 0; o >>= 1) p += __shfl_down_sync(0xffffffffu, p, o);
    __shared__ float red[8];
    if ((tid & 31) == 0) red[tid >> 5] = p;
    __syncthreads();
    if (tid == 0){
        float c = b1[f];
#pragma unroll
        for (int w = 0; w < 8; w++) c += red[w];
        int e0 = eidx[2*n], e1 = eidx[2*n+1];
        float l0 = 0.f, l1 = 0.f;
#pragma unroll
        for (int r = 0; r < 8; r++){
            l0 += z1c[n*16+r]   * B1[((size_t)e0*F_DIM+f)*R_RANK + r];
            l1 += z1c[n*16+8+r] * B1[((size_t)e1*F_DIM+f)*R_RANK + r];
        }
        float h0 = gelu_new(c + l0), h1 = gelu_new(c + l1);
        float hg0 = __half2float(h16a[(size_t)n*F_DIM + f]);
        float hg1 = __half2float(h16b[(size_t)n*F_DIM + f]);
        if (fabsf(hg0 - h0) > 4e-3f*fmaxf(1.f, fabsf(h0)) ||
            fabsf(hg1 - h1) > 4e-3f*fmaxf(1.f, fabsf(h1)))
            atomicAdd(&gf1, 1);
    }
}

__global__ __launch_bounds__(256) void ver_fc2(
    const float* __restrict__ W2, const float* __restrict__ b2,
    const float* __restrict__ B2, const float* __restrict__ out)
{
    int s = blockIdx.x, tid = threadIdx.x;
    int n = (s * 89 + 3) & (N_TOK - 1);
    int d = (s * 41 + 5) & (D_DIM - 1);
    float p = 0.f;
    for (int f = tid; f < F_DIM; f += 256)
        p += (__half2float(g16h[(size_t)n*F_DIM + f]) +
              __half2float(g16l[(size_t)n*F_DIM + f])) * W2[(size_t)d*F_DIM + f];
    for (int o = 16; o > 0; o >>= 1) p += __shfl_down_sync(0xffffffffu, p, o);
    __shared__ float red[8];
    if ((tid & 31) == 0) red[tid >> 5] = p;
    __syncthreads();
    if (tid == 0){
        float c = wsum_buf[n] * b2[d];
#pragma unroll
        for (int w = 0; w < 8; w++) c += red[w];
        int e0 = eidx[2*n], e1 = eidx[2*n+1];
#pragma unroll
        for (int r = 0; r < 8; r++){
            c += z2s[n*16+r]   * B2[((size_t)e0*D_DIM+d)*R_RANK + r];
            c += z2s[n*16+8+r] * B2[((size_t)e1*D_DIM+d)*R_RANK + r];
        }
        float o_ = out[(size_t)n*D_DIM + d];
        if (fabsf(o_ - c) > 4e-3f*fmaxf(1.f, fabsf(c)))
            atomicAdd(&gf2, 1);
    }
}

__global__ __launch_bounds__(256, 2) void fc1_fb(
    const float* __restrict__ A, const float* __restrict__ B,
    const float* __restrict__ b1, const float* __restrict__ B1)
{
    if (gf1 == 0) return;
    const int K = D_DIM;
    int bn = blockIdx.x, bm = blockIdx.y;
    int tid = threadIdx.x;
    __shared__ float As[BK][BM + 4];
    __shared__ float Bs[BK][BN + 4];
    float acc[TM][TN];
#pragma unroll
    for (int i = 0; i < TM; i++)
#pragma unroll
        for (int j = 0; j < TN; j++) acc[i][j] = 0.f;
    int tx = tid % 16, ty = tid / 16;
    const float* Ab = A + (size_t)bm * BM * K;
    const float* Bb = B + (size_t)bn * BN * K;
    int rowL = tid >> 2;
    int colL = (tid & 3) * 4;
    for (int k0 = 0; k0 < K; k0 += BK) {
#pragma unroll
        for (int i = 0; i < 2; i++) {
            float4 a = *(const float4*)(Ab + (size_t)(rowL + i * 64) * K + k0 + colL);
            As[colL + 0][rowL + i * 64] = a.x;
            As[colL + 1][rowL + i * 64] = a.y;
            As[colL + 2][rowL + i * 64] = a.z;
            As[colL + 3][rowL + i * 64] = a.w;
            float4 b = *(const float4*)(Bb + (size_t)(rowL + i * 64) * K + k0 + colL);
            Bs[colL + 0][rowL + i * 64] = b.x;
            Bs[colL + 1][rowL + i * 64] = b.y;
            Bs[colL + 2][rowL + i * 64] = b.z;
            Bs[colL + 3][rowL + i * 64] = b.w;
        }
        __syncthreads();
#pragma unroll
        for (int kk = 0; kk < BK; kk++) {
            float4 a0 = *(const float4*)&As[kk][ty * TM];
            float4 a1 = *(const float4*)&As[kk][ty * TM + 4];
            float4 b0 = *(const float4*)&Bs[kk][tx * TN];
            float4 b1v = *(const float4*)&Bs[kk][tx * TN + 4];
            float ra[8] = {a0.x, a0.y, a0.z, a0.w, a1.x, a1.y, a1.z, a1.w};
            float rb[8] = {b0.x, b0.y, b0.z, b0.w, b1v.x, b1v.y, b1v.z, b1v.w};
#pragma unroll
            for (int i = 0; i < TM; i++)
#pragma unroll
                for (int j = 0; j < TN; j++) acc[i][j] += ra[i] * rb[j];
        }
        __syncthreads();
    }
    int nrow0 = bm * BM + ty * TM;
    int fcol0 = bn * BN + tx * TN;
#pragma unroll
    for (int i = 0; i < TM; i++) {
        int n = nrow0 + i;
        int e0 = eidx[2 * n], e1 = eidx[2 * n + 1];
        float w0 = ew[2 * n], w1 = ew[2 * n + 1];
        const float4* zp = (const float4*)&z1c[n * 16];
        float4 z0a = zp[0], z0b = zp[1], z1a = zp[2], z1b = zp[3];
#pragma unroll
        for (int j = 0; j < TN; j++) {
            int f = fcol0 + j;
            float c = acc[i][j] + b1[f];
            const float4* q0 = (const float4*)&B1[((size_t)e0 * F_DIM + f) * R_RANK];
            float4 u0 = q0[0], u1 = q0[1];
            float l0 = z0a.x * u0.x + z0a.y * u0.y + z0a.z * u0.z + z0a.w * u0.w
                     + z0b.x * u1.x + z0b.y * u1.y + z0b.z * u1.z + z0b.w * u1.w;
            const float4* q1 = (const float4*)&B1[((size_t)e1 * F_DIM + f) * R_RANK];
            float4 v0 = q1[0], v1 = q1[1];
            float l1 = z1a.x * v0.x + z1a.y * v0.y + z1a.z * v0.z + z1a.w * v0.w
                     + z1b.x * v1.x + z1b.y * v1.y + z1b.z * v1.z + z1b.w * v1.w;
            float h0 = gelu_new(c + l0);
            float h1 = gelu_new(c + l1);
            float g = w0 * h0 + w1 * h1;
            size_t off = (size_t)n * F_DIM + f;
            h16a[off] = __float2half_rn(h0);
            h16b[off] = __float2half_rn(h1);
            __half gh = __float2half_rn(g);
            g16h[off] = gh;
            g16l[off] = __float2half_rn(g - __half2float(gh));
        }
    }
}

__global__ __launch_bounds__(256, 2) void fc2_fb(
    const float* __restrict__ B, const float* __restrict__ b2,
    const float* __restrict__ B2, float* __restrict__ out)
{
    if (gf2 == 0 && gf1 == 0) return;
    const int K = F_DIM;
    int bn = blockIdx.x, bm = blockIdx.y;
    int tid = threadIdx.x;
    __shared__ float As[BK][BM + 4];
    __shared__ float Bs[BK][BN + 4];
    float acc[TM][TN];
#pragma unroll
    for (int i = 0; i < TM; i++)
#pragma unroll
        for (int j = 0; j < TN; j++) acc[i][j] = 0.f;
    int tx = tid % 16, ty = tid / 16;
    const __half* Ahp = g16h + (size_t)bm * BM * K;
    const __half* Alp = g16l + (size_t)bm * BM * K;
    const float* Bb = B + (size_t)bn * BN * K;
    int rowL = tid >> 2;
    int colL = (tid & 3) * 4;
    for (int k0 = 0; k0 < K; k0 += BK) {
#pragma unroll
        for (int i = 0; i < 2; i++) {
            size_t ao = (size_t)(rowL + i * 64) * K + k0 + colL;
            uint2 hv = *(const uint2*)(Ahp + ao);
            uint2 lv = *(const uint2*)(Alp + ao);
            float2 h0 = __half22float2(*(__half2*)&hv.x);
            float2 h1 = __half22float2(*(__half2*)&hv.y);
            float2 l0 = __half22float2(*(__half2*)&lv.x);
            float2 l1 = __half22float2(*(__half2*)&lv.y);
            As[colL + 0][rowL + i * 64] = h0.x + l0.x;
            As[colL + 1][rowL + i * 64] = h0.y + l0.y;
            As[colL + 2][rowL + i * 64] = h1.x + l1.x;
            As[colL + 3][rowL + i * 64] = h1.y + l1.y;
            float4 b = *(const float4*)(Bb + ao);
            Bs[colL + 0][rowL + i * 64] = b.x;
            Bs[colL + 1][rowL + i * 64] = b.y;
            Bs[colL + 2][rowL + i * 64] = b.z;
            Bs[colL + 3][rowL + i * 64] = b.w;
        }
        __syncthreads();
#pragma unroll
        for (int kk = 0; kk < BK; kk++) {
            float4 a0 = *(const float4*)&As[kk][ty * TM];
            float4 a1 = *(const float4*)&As[kk][ty * TM + 4];
            float4 b0 = *(const float4*)&Bs[kk][tx * TN];
            float4 b1v = *(const float4*)&Bs[kk][tx * TN + 4];
            float ra[8] = {a0.x, a0.y, a0.z, a0.w, a1.x, a1.y, a1.z, a1.w};
            float rb[8] = {b0.x, b0.y, b0.z, b0.w, b1v.x, b1v.y, b1v.z, b1v.w};
#pragma unroll
            for (int i = 0; i < TM; i++)
#pragma unroll
                for (int j = 0; j < TN; j++) acc[i][j] += ra[i] * rb[j];
        }
        __syncthreads();
    }
    int nrow0 = bm * BM + ty * TM;
    int dcol0 = bn * BN + tx * TN;
#pragma unroll
    for (int i = 0; i < TM; i++) {
        int n = nrow0 + i;
        float ws = wsum_buf[n];
        int e0 = eidx[2 * n], e1 = eidx[2 * n + 1];
        const float4* zp = (const float4*)&z2s[n * 16];
        float4 z0a = zp[0], z0b = zp[1], z1a = zp[2], z1b = zp[3];
#pragma unroll
        for (int j = 0; j < TN; j++) {
            int d = dcol0 + j;
            float c = acc[i][j] + ws * b2[d];
            const float4* q0 = (const float4*)&B2[((size_t)e0 * D_DIM + d) * R_RANK];
            float4 u0 = q0[0], u1 = q0[1];
            c += z0a.x * u0.x + z0a.y * u0.y + z0a.z * u0.z + z0a.w * u0.w
               + z0b.x * u1.x + z0b.y * u1.y + z0b.z * u1.z + z0b.w * u1.w;
            const float4* q1 = (const float4*)&B2[((size_t)e1 * D_DIM + d) * R_RANK];
            float4 v0 = q1[0], v1 = q1[1];
            c += z1a.x * v0.x + z1a.y * v0.y + z1a.z * v0.z + z1a.w * v0.w
               + z1b.x * v1.x + z1b.y * v1.y + z1b.z * v1.z + z1b.w * v1.w;
            out[(size_t)n * D_DIM + d] = c;
        }
    }
}

// ------------------------- launch ------------------------------------------
extern "C" void kernel_launch(void* const* d_in, const int* in_sizes, int n_in,
                              void* d_out, int out_size)
{
    (void)in_sizes; (void)n_in; (void)out_size;
    const float* x  = (const float*)d_in[0];
    const float* Wr = (const float*)d_in[1];
    const float* br = (const float*)d_in[2];
    const float* W1 = (const float*)d_in[3];
    const float* b1 = (const float*)d_in[4];
    const float* W2 = (const float*)d_in[5];
    const float* b2 = (const float*)d_in[6];
    const float* A1 = (const float*)d_in[7];
    const float* B1 = (const float*)d_in[8];
    const float* A2 = (const float*)d_in[9];
    const float* B2 = (const float*)d_in[10];
    float* out = (float*)d_out;

    reset_kernel<<<1, 1>>>();
    router_kernel<<<N_TOK, 256>>>(x, Wr, br, A1);
    cvt16<<<N_TOK, 256>>>(x,  x16h,  x16l,  D_DIM);
    cvt16<<<F_DIM, 256>>>(W1, w1h16, w1l16, D_DIM);
    cvt16<<<D_DIM, 256>>>(W2, w2h16, w2l16, F_DIM);

    fc1_f16<<<dim3(F_DIM/128, N_TOK/128), 256>>>(b1, B1);
    ver_fc1<<<1024, 256>>>(x, W1, b1, B1);
    fc1_fb<<<dim3(F_DIM/BN, N_TOK/BM), 256>>>(x, W1, b1, B1);

    z2_kernel<<<dim3(N_TOK, 2), 256>>>(A2);

    fc2_f16<<<dim3(D_DIM/128, N_TOK/128), 256>>>(b2, B2, out);
    ver_fc2<<<512, 256>>>(W2, b2, B2, out);
    fc2_fb<<<dim3(D_DIM/BN, N_TOK/BM), 256>>>(W2, b2, B2, out);
}

// round 14
// speedup vs baseline: 2.0181x; 2.0181x over previous
#include <cuda_runtime.h>
#include <cuda_fp16.h>
#include <mma.h>
#include <math.h>
#include <stdint.h>

using namespace nvcuda;

#define N_TOK 4096
#define D_DIM 2048
#define F_DIM 8192
#define E_EXP 8
#define R_RANK 8
#define SCALING 2.0f

#define BM 128
#define BN 128
#define BK 16
#define TM 8
#define TN 8

// token-tile split: 18 SIMT tiles, 14 tensor tiles (of 32)
#define TSPLIT 18

// tensor smem tile geometry
#define TSTRIDE 24
#define TSIZE   (128 * TSTRIDE)
#define STAGE   (4 * TSIZE)          // halves per stage; 2 stages = 49152 B

// ---------------- scratch (~264MB — below known-good R12 level) --------------
__device__ float  g_buf[(size_t)N_TOK * F_DIM];
__device__ __half h16a[(size_t)N_TOK * F_DIM];
__device__ __half h16b[(size_t)N_TOK * F_DIM];
__device__ float z1c[N_TOK * 16];
__device__ float z2s[N_TOK * 16];
__device__ int   eidx[N_TOK * 2];
__device__ float ew[N_TOK * 2];
__device__ float wsum_buf[N_TOK];

__device__ __forceinline__ float gelu_new(float x) {
    float x3 = x * x * x;
    float t = tanhf(0.7978845608028654f * (x + 0.044715f * x3));
    return 0.5f * x * (1.0f + t);
}
__device__ __forceinline__ uint32_t h2u(__half2 h){ return *(uint32_t*)&h; }
__device__ __forceinline__ uint32_t pkh(float a, float b){
    return h2u(__halves2half2(__float2half_rn(a), __float2half_rn(b)));
}

// ---------------- router — verbatim R1 ---------------------------------------
__global__ __launch_bounds__(256) void router_kernel(
    const float* __restrict__ x, const float* __restrict__ Wr,
    const float* __restrict__ br, const float* __restrict__ A1)
{
    int n = blockIdx.x;
    int tid = threadIdx.x;
    __shared__ float xs[D_DIM];
    __shared__ float red[16][8];
    __shared__ int s_idx[2];

    for (int d = tid; d < D_DIM; d += 256) xs[d] = x[(size_t)n * D_DIM + d];
    __syncthreads();

    float acc[E_EXP];
#pragma unroll
    for (int e = 0; e < E_EXP; e++) acc[e] = 0.f;
    for (int d = tid; d < D_DIM; d += 256) {
        float xv = xs[d];
#pragma unroll
        for (int e = 0; e < E_EXP; e++) acc[e] += xv * Wr[e * D_DIM + d];
    }
#pragma unroll
    for (int e = 0; e < E_EXP; e++) {
        float v = acc[e];
        for (int o = 16; o > 0; o >>= 1) v += __shfl_down_sync(0xffffffffu, v, o);
        if ((tid & 31) == 0) red[e][tid >> 5] = v;
    }
    __syncthreads();

    if (tid == 0) {
        float lg[E_EXP];
#pragma unroll
        for (int e = 0; e < E_EXP; e++) {
            float v = 0.f;
#pragma unroll
            for (int w = 0; w < 8; w++) v += red[e][w];
            lg[e] = v + br[e];
        }
        float mx = lg[0];
#pragma unroll
        for (int e = 1; e < E_EXP; e++) mx = fmaxf(mx, lg[e]);
        float p[E_EXP], se = 0.f;
#pragma unroll
        for (int e = 0; e < E_EXP; e++) { p[e] = expf(lg[e] - mx); se += p[e]; }
        float inv = 1.0f / se;
#pragma unroll
        for (int e = 0; e < E_EXP; e++) p[e] *= inv;
        int i0 = 0;
#pragma unroll
        for (int e = 1; e < E_EXP; e++) if (p[e] > p[i0]) i0 = e;
        int i1 = -1;
#pragma unroll
        for (int e = 0; e < E_EXP; e++) {
            if (e == i0) continue;
            if (i1 < 0 || p[e] > p[i1]) i1 = e;
        }
        s_idx[0] = i0; s_idx[1] = i1;
        eidx[2 * n] = i0; eidx[2 * n + 1] = i1;
        ew[2 * n] = p[i0]; ew[2 * n + 1] = p[i1];
        wsum_buf[n] = p[i0] + p[i1];
    }
    __syncthreads();

    int e0 = s_idx[0], e1 = s_idx[1];
    float u[16];
#pragma unroll
    for (int i = 0; i < 16; i++) u[i] = 0.f;
    for (int d = tid; d < D_DIM; d += 256) {
        float xv = xs[d];
#pragma unroll
        for (int r = 0; r < R_RANK; r++) {
            u[r]     += xv * A1[((size_t)e0 * R_RANK + r) * D_DIM + d];
            u[8 + r] += xv * A1[((size_t)e1 * R_RANK + r) * D_DIM + d];
        }
    }
    __syncthreads();
#pragma unroll
    for (int i = 0; i < 16; i++) {
        float v = u[i];
        for (int o = 16; o > 0; o >>= 1) v += __shfl_down_sync(0xffffffffu, v, o);
        if ((tid & 31) == 0) red[i][tid >> 5] = v;
    }
    __syncthreads();
    if (tid < 16) {
        float v = 0.f;
#pragma unroll
        for (int w = 0; w < 8; w++) v += red[tid][w];
        z1c[n * 16 + tid] = v * SCALING;
    }
}

// ============================================================================
// tensor machinery: fp16 x3 GEMM with on-the-fly fp32->fp16 hi/lo conversion
// ============================================================================
typedef wmma::fragment<wmma::matrix_a, 16,16,16, __half, wmma::row_major> HA;
typedef wmma::fragment<wmma::matrix_b, 16,16,16, __half, wmma::col_major> HB;
typedef wmma::fragment<wmma::accumulator, 16,16,16, float> HC;

__device__ __forceinline__ void cvt_store8(__half* base, int so, float4 v0, float4 v1){
    __half2 h0 = __halves2half2(__float2half_rn(v0.x), __float2half_rn(v0.y));
    __half2 h1 = __halves2half2(__float2half_rn(v0.z), __float2half_rn(v0.w));
    __half2 h2 = __halves2half2(__float2half_rn(v1.x), __float2half_rn(v1.y));
    __half2 h3 = __halves2half2(__float2half_rn(v1.z), __float2half_rn(v1.w));
    float2 f0 = __half22float2(h0), f1 = __half22float2(h1);
    float2 f2 = __half22float2(h2), f3 = __half22float2(h3);
    __half2 l0 = __halves2half2(__float2half_rn(v0.x - f0.x), __float2half_rn(v0.y - f0.y));
    __half2 l1 = __halves2half2(__float2half_rn(v0.z - f1.x), __float2half_rn(v0.w - f1.y));
    __half2 l2 = __halves2half2(__float2half_rn(v1.x - f2.x), __float2half_rn(v1.y - f2.y));
    __half2 l3 = __halves2half2(__float2half_rn(v1.z - f3.x), __float2half_rn(v1.w - f3.y));
    *(uint4*)(base + so)         = make_uint4(h2u(h0), h2u(h1), h2u(h2), h2u(h3));
    *(uint4*)(base + TSIZE + so) = make_uint4(h2u(l0), h2u(l1), h2u(l2), h2u(l3));
}

__device__ __forceinline__ void gemm16cv(
    HC (&acc)[2][4],
    const float* Af, const float* Bf, int K, __half* sm)
{
    const int tid = threadIdx.x, wid = tid >> 5;
    const int wr = wid & 3, wc = wid >> 2;
    const int row = tid >> 1, hf = (tid & 1) * 8;
    const int so = row * TSTRIDE + hf;
#pragma unroll
    for (int i = 0; i < 2; i++)
#pragma unroll
    for (int j = 0; j < 4; j++) wmma::fill_fragment(acc[i][j], 0.f);

    const float* ap = Af + (size_t)row * K + hf;
    const float* bp = Bf + (size_t)row * K + hf;
    float4 a0 = *(const float4*)ap,      a1 = *(const float4*)(ap + 4);
    float4 b0 = *(const float4*)bp,      b1 = *(const float4*)(bp + 4);
    cvt_store8(sm, so, a0, a1);
    cvt_store8(sm + 2*TSIZE, so, b0, b1);
    __syncthreads();

    const int nch = K / 16;
    for (int c = 0; c < nch; c++){
        if (c + 1 < nch){
            a0 = *(const float4*)(ap + (c+1)*16);
            a1 = *(const float4*)(ap + (c+1)*16 + 4);
            b0 = *(const float4*)(bp + (c+1)*16);
            b1 = *(const float4*)(bp + (c+1)*16 + 4);
        }
        const __half* st = sm + (c & 1) * STAGE;
        HA ah[2], al[2];
#pragma unroll
        for (int i = 0; i < 2; i++){
            wmma::load_matrix_sync(ah[i], st + (wr*32 + i*16)*TSTRIDE, TSTRIDE);
            wmma::load_matrix_sync(al[i], st + TSIZE + (wr*32 + i*16)*TSTRIDE, TSTRIDE);
        }
#pragma unroll
        for (int j = 0; j < 4; j++){
            HB bh, bl;
            wmma::load_matrix_sync(bh, st + 2*TSIZE + (wc*64 + j*16)*TSTRIDE, TSTRIDE);
            wmma::load_matrix_sync(bl, st + 3*TSIZE + (wc*64 + j*16)*TSTRIDE, TSTRIDE);
#pragma unroll
            for (int i = 0; i < 2; i++){
                wmma::mma_sync(acc[i][j], ah[i], bh, acc[i][j]);
                wmma::mma_sync(acc[i][j], ah[i], bl, acc[i][j]);
                wmma::mma_sync(acc[i][j], al[i], bh, acc[i][j]);
            }
        }
        if (c + 1 < nch){
            __half* d = sm + ((c + 1) & 1) * STAGE;
            cvt_store8(d, so, a0, a1);
            cvt_store8(d + 2*TSIZE, so, b0, b1);
        }
        __syncthreads();
    }
}

// ============================================================================
// fc1 hybrid kernel
// ============================================================================
__device__ void fc1_simt(int bm, int bn, char* smem_u,
    const float* __restrict__ A, const float* __restrict__ B,
    const float* __restrict__ b1, const float* __restrict__ B1)
{
    const int K = D_DIM;
    int tid = threadIdx.x;
    float* As = (float*)smem_u;                 // [16][132]
    float* Bs = As + 16 * 132;                  // [16][132]
    float acc[TM][TN];
#pragma unroll
    for (int i = 0; i < TM; i++)
#pragma unroll
        for (int j = 0; j < TN; j++) acc[i][j] = 0.f;

    int tx = tid % 16, ty = tid / 16;
    const float* Ab = A + (size_t)bm * BM * K;
    const float* Bb = B + (size_t)bn * BN * K;
    int rowL = tid >> 2;
    int colL = (tid & 3) * 4;

    for (int k0 = 0; k0 < K; k0 += BK) {
#pragma unroll
        for (int i = 0; i < 2; i++) {
            float4 a = *(const float4*)(Ab + (size_t)(rowL + i * 64) * K + k0 + colL);
            As[(colL + 0) * 132 + rowL + i * 64] = a.x;
            As[(colL + 1) * 132 + rowL + i * 64] = a.y;
            As[(colL + 2) * 132 + rowL + i * 64] = a.z;
            As[(colL + 3) * 132 + rowL + i * 64] = a.w;
            float4 b = *(const float4*)(Bb + (size_t)(rowL + i * 64) * K + k0 + colL);
            Bs[(colL + 0) * 132 + rowL + i * 64] = b.x;
            Bs[(colL + 1) * 132 + rowL + i * 64] = b.y;
            Bs[(colL + 2) * 132 + rowL + i * 64] = b.z;
            Bs[(colL + 3) * 132 + rowL + i * 64] = b.w;
        }
        __syncthreads();
#pragma unroll
        for (int kk = 0; kk < BK; kk++) {
            float4 a0 = *(const float4*)&As[kk * 132 + ty * TM];
            float4 a1 = *(const float4*)&As[kk * 132 + ty * TM + 4];
            float4 b0 = *(const float4*)&Bs[kk * 132 + tx * TN];
            float4 b1v = *(const float4*)&Bs[kk * 132 + tx * TN + 4];
            float ra[8] = {a0.x, a0.y, a0.z, a0.w, a1.x, a1.y, a1.z, a1.w};
            float rb[8] = {b0.x, b0.y, b0.z, b0.w, b1v.x, b1v.y, b1v.z, b1v.w};
#pragma unroll
            for (int i = 0; i < TM; i++)
#pragma unroll
                for (int j = 0; j < TN; j++) acc[i][j] += ra[i] * rb[j];
        }
        __syncthreads();
    }

    int nrow0 = bm * BM + ty * TM;
    int fcol0 = bn * BN + tx * TN;
#pragma unroll
    for (int i = 0; i < TM; i++) {
        int n = nrow0 + i;
        int e0 = eidx[2 * n], e1 = eidx[2 * n + 1];
        float w0 = ew[2 * n], w1 = ew[2 * n + 1];
        const float4* zp = (const float4*)&z1c[n * 16];
        float4 z0a = zp[0], z0b = zp[1], z1a = zp[2], z1b = zp[3];
        float h0v[TN], h1v[TN], gv[TN];
#pragma unroll
        for (int j = 0; j < TN; j++) {
            int f = fcol0 + j;
            float c = acc[i][j] + b1[f];
            const float4* q0 = (const float4*)&B1[((size_t)e0 * F_DIM + f) * R_RANK];
            float4 u0 = q0[0], u1 = q0[1];
            float l0 = z0a.x * u0.x + z0a.y * u0.y + z0a.z * u0.z + z0a.w * u0.w
                     + z0b.x * u1.x + z0b.y * u1.y + z0b.z * u1.z + z0b.w * u1.w;
            const float4* q1 = (const float4*)&B1[((size_t)e1 * F_DIM + f) * R_RANK];
            float4 v0 = q1[0], v1 = q1[1];
            float l1 = z1a.x * v0.x + z1a.y * v0.y + z1a.z * v0.z + z1a.w * v0.w
                     + z1b.x * v1.x + z1b.y * v1.y + z1b.z * v1.z + z1b.w * v1.w;
            float h0 = gelu_new(c + l0);
            float h1 = gelu_new(c + l1);
            h0v[j] = h0; h1v[j] = h1;
            gv[j] = w0 * h0 + w1 * h1;
        }
        size_t off = (size_t)n * F_DIM + fcol0;
        *(uint4*)&h16a[off] = make_uint4(pkh(h0v[0],h0v[1]), pkh(h0v[2],h0v[3]),
                                         pkh(h0v[4],h0v[5]), pkh(h0v[6],h0v[7]));
        *(uint4*)&h16b[off] = make_uint4(pkh(h1v[0],h1v[1]), pkh(h1v[2],h1v[3]),
                                         pkh(h1v[4],h1v[5]), pkh(h1v[6],h1v[7]));
        *(float4*)&g_buf[off]     = make_float4(gv[0], gv[1], gv[2], gv[3]);
        *(float4*)&g_buf[off + 4] = make_float4(gv[4], gv[5], gv[6], gv[7]);
    }
}

__device__ void fc1_tens(int bm, int bn, char* smem_u,
    const float* __restrict__ x, const float* __restrict__ W1,
    const float* __restrict__ b1, const float* __restrict__ B1)
{
    __half* smh = (__half*)smem_u;
    int tid = threadIdx.x, wid = tid >> 5, wr = wid & 3, wc = wid >> 2;
    HC acc[2][4];
    gemm16cv(acc, x + (size_t)bm*128*D_DIM, W1 + (size_t)bn*128*D_DIM, D_DIM, smh);

    float* Cs = (float*)smem_u;   // 64 x 136 floats
    for (int r = 0; r < 2; r++){
        __syncthreads();
        if ((wr >> 1) == r){
            int rl = (wr & 1) * 32;
#pragma unroll
            for (int i = 0; i < 2; i++)
#pragma unroll
            for (int j = 0; j < 4; j++)
                wmma::store_matrix_sync(Cs + (size_t)(rl+i*16)*136 + wc*64 + j*16,
                                        acc[i][j], 136, wmma::mem_row_major);
        }
        __syncthreads();

        int row_l = tid >> 2;
        int n = bm*128 + r*64 + row_l;
        int c0 = (tid & 3) * 32;
        int e0 = eidx[2*n], e1 = eidx[2*n+1];
        float w0 = ew[2*n], w1w = ew[2*n+1];
        float z0[8], z1[8];
#pragma unroll
        for (int q = 0; q < 8; q++){ z0[q] = z1c[n*16+q]; z1[q] = z1c[n*16+8+q]; }
        const float* crow = &Cs[(size_t)row_l*136];
        for (int jj = 0; jj < 32; jj += 2){
            int col = c0 + jj;
            int f = bn*128 + col;
            float ca = crow[col]   + b1[f];
            float cb = crow[col+1] + b1[f+1];
            const float4* q0 = (const float4*)&B1[((size_t)e0*F_DIM + f)*R_RANK];
            const float4* q1 = (const float4*)&B1[((size_t)e1*F_DIM + f)*R_RANK];
            float l0a=0.f, l0b=0.f, l1a=0.f, l1b=0.f;
#pragma unroll
            for (int q = 0; q < 2; q++){
                float4 u0=q0[q], u2=q0[2+q], v0=q1[q], v2=q1[2+q];
                l0a += z0[q*4+0]*u0.x + z0[q*4+1]*u0.y + z0[q*4+2]*u0.z + z0[q*4+3]*u0.w;
                l0b += z0[q*4+0]*u2.x + z0[q*4+1]*u2.y + z0[q*4+2]*u2.z + z0[q*4+3]*u2.w;
                l1a += z1[q*4+0]*v0.x + z1[q*4+1]*v0.y + z1[q*4+2]*v0.z + z1[q*4+3]*v0.w;
                l1b += z1[q*4+0]*v2.x + z1[q*4+1]*v2.y + z1[q*4+2]*v2.z + z1[q*4+3]*v2.w;
            }
            float h0a = gelu_new(ca + l0a), h0b_ = gelu_new(cb + l0b);
            float h1a = gelu_new(ca + l1a), h1b_ = gelu_new(cb + l1b);
            size_t off = (size_t)n*F_DIM + f;
            *(uint32_t*)&h16a[off] = pkh(h0a, h0b_);
            *(uint32_t*)&h16b[off] = pkh(h1a, h1b_);
            *(float2*)&g_buf[off] = make_float2(w0*h0a + w1w*h1a, w0*h0b_ + w1w*h1b_);
        }
    }
}

__global__ __launch_bounds__(256, 2) void fc1_hyb(
    const float* __restrict__ x, const float* __restrict__ W1,
    const float* __restrict__ b1, const float* __restrict__ B1)
{
    __shared__ __align__(16) char smem_u[49152];
    int b = blockIdx.x, slot = b & 15, grp = b >> 4;
    if (slot < 9){
        int i = grp * 9 + slot;          // [0,1152)
        fc1_simt(i / 64, i % 64, smem_u, x, W1, b1, B1);
    } else {
        int j = grp * 7 + (slot - 9);    // [0,896)
        fc1_tens(TSPLIT + j / 64, j % 64, smem_u, x, W1, b1, B1);
    }
}

// ============================================================================
// z2 — R13-verified (reads fp16 h planes)
// ============================================================================
__global__ __launch_bounds__(256) void z2_kernel(const float* __restrict__ A2)
{
    int n = blockIdx.x;
    int k = blockIdx.y;
    int tid = threadIdx.x;
    int e = eidx[2 * n + k];
    const __half* h = (k ? h16b : h16a) + (size_t)n * F_DIM;
    const float* a2 = A2 + (size_t)e * R_RANK * F_DIM;

    float acc[R_RANK];
#pragma unroll
    for (int r = 0; r < R_RANK; r++) acc[r] = 0.f;

    for (int f = tid * 4; f < F_DIM; f += 1024) {
        uint2 hp = *(const uint2*)(h + f);
        float2 f0 = __half22float2(*(__half2*)&hp.x);
        float2 f1 = __half22float2(*(__half2*)&hp.y);
#pragma unroll
        for (int r = 0; r < R_RANK; r++) {
            float4 av = *(const float4*)(a2 + (size_t)r * F_DIM + f);
            acc[r] += f0.x * av.x + f0.y * av.y + f1.x * av.z + f1.y * av.w;
        }
    }
    __shared__ float red[R_RANK][8];
#pragma unroll
    for (int r = 0; r < R_RANK; r++) {
        float v = acc[r];
        for (int o = 16; o > 0; o >>= 1) v += __shfl_down_sync(0xffffffffu, v, o);
        if ((tid & 31) == 0) red[r][tid >> 5] = v;
    }
    __syncthreads();
    if (tid < R_RANK) {
        float v = 0.f;
#pragma unroll
        for (int w = 0; w < 8; w++) v += red[tid][w];
        z2s[n * 16 + k * 8 + tid] = v * SCALING * ew[2 * n + k];
    }
}

// ============================================================================
// fc2 hybrid kernel
// ============================================================================
__device__ void fc2_simt(int bm, int bn, char* smem_u,
    const float* __restrict__ B, const float* __restrict__ b2,
    const float* __restrict__ B2, float* __restrict__ out)
{
    const int K = F_DIM;
    int tid = threadIdx.x;
    float* As = (float*)smem_u;
    float* Bs = As + 16 * 132;
    float acc[TM][TN];
#pragma unroll
    for (int i = 0; i < TM; i++)
#pragma unroll
        for (int j = 0; j < TN; j++) acc[i][j] = 0.f;

    int tx = tid % 16, ty = tid / 16;
    const float* Ab = g_buf + (size_t)bm * BM * K;
    const float* Bb = B + (size_t)bn * BN * K;
    int rowL = tid >> 2;
    int colL = (tid & 3) * 4;

    for (int k0 = 0; k0 < K; k0 += BK) {
#pragma unroll
        for (int i = 0; i < 2; i++) {
            float4 a = *(const float4*)(Ab + (size_t)(rowL + i * 64) * K + k0 + colL);
            As[(colL + 0) * 132 + rowL + i * 64] = a.x;
            As[(colL + 1) * 132 + rowL + i * 64] = a.y;
            As[(colL + 2) * 132 + rowL + i * 64] = a.z;
            As[(colL + 3) * 132 + rowL + i * 64] = a.w;
            float4 b = *(const float4*)(Bb + (size_t)(rowL + i * 64) * K + k0 + colL);
            Bs[(colL + 0) * 132 + rowL + i * 64] = b.x;
            Bs[(colL + 1) * 132 + rowL + i * 64] = b.y;
            Bs[(colL + 2) * 132 + rowL + i * 64] = b.z;
            Bs[(colL + 3) * 132 + rowL + i * 64] = b.w;
        }
        __syncthreads();
#pragma unroll
        for (int kk = 0; kk < BK; kk++) {
            float4 a0 = *(const float4*)&As[kk * 132 + ty * TM];
            float4 a1 = *(const float4*)&As[kk * 132 + ty * TM + 4];
            float4 b0 = *(const float4*)&Bs[kk * 132 + tx * TN];
            float4 b1v = *(const float4*)&Bs[kk * 132 + tx * TN + 4];
            float ra[8] = {a0.x, a0.y, a0.z, a0.w, a1.x, a1.y, a1.z, a1.w};
            float rb[8] = {b0.x, b0.y, b0.z, b0.w, b1v.x, b1v.y, b1v.z, b1v.w};
#pragma unroll
            for (int i = 0; i < TM; i++)
#pragma unroll
                for (int j = 0; j < TN; j++) acc[i][j] += ra[i] * rb[j];
        }
        __syncthreads();
    }

    int nrow0 = bm * BM + ty * TM;
    int dcol0 = bn * BN + tx * TN;
#pragma unroll
    for (int i = 0; i < TM; i++) {
        int n = nrow0 + i;
        float ws = wsum_buf[n];
        int e0 = eidx[2 * n], e1 = eidx[2 * n + 1];
        const float4* zp = (const float4*)&z2s[n * 16];
        float4 z0a = zp[0], z0b = zp[1], z1a = zp[2], z1b = zp[3];
        float ov[TN];
#pragma unroll
        for (int j = 0; j < TN; j++) {
            int d = dcol0 + j;
            float c = acc[i][j] + ws * b2[d];
            const float4* q0 = (const float4*)&B2[((size_t)e0 * D_DIM + d) * R_RANK];
            float4 u0 = q0[0], u1 = q0[1];
            c += z0a.x * u0.x + z0a.y * u0.y + z0a.z * u0.z + z0a.w * u0.w
               + z0b.x * u1.x + z0b.y * u1.y + z0b.z * u1.z + z0b.w * u1.w;
            const float4* q1 = (const float4*)&B2[((size_t)e1 * D_DIM + d) * R_RANK];
            float4 v0 = q1[0], v1 = q1[1];
            c += z1a.x * v0.x + z1a.y * v0.y + z1a.z * v0.z + z1a.w * v0.w
               + z1b.x * v1.x + z1b.y * v1.y + z1b.z * v1.z + z1b.w * v1.w;
            ov[j] = c;
        }
        size_t off = (size_t)n * D_DIM + dcol0;
        *(float4*)&out[off]     = make_float4(ov[0], ov[1], ov[2], ov[3]);
        *(float4*)&out[off + 4] = make_float4(ov[4], ov[5], ov[6], ov[7]);
    }
}

__device__ void fc2_tens(int bm, int bn, char* smem_u,
    const float* __restrict__ W2, const float* __restrict__ b2,
    const float* __restrict__ B2, float* __restrict__ out)
{
    __half* smh = (__half*)smem_u;
    int tid = threadIdx.x, wid = tid >> 5, wr = wid & 3, wc = wid >> 2;
    HC acc[2][4];
    gemm16cv(acc, g_buf + (size_t)bm*128*F_DIM, W2 + (size_t)bn*128*F_DIM, F_DIM, smh);

    float* Cs = (float*)smem_u;
    for (int r = 0; r < 2; r++){
        __syncthreads();
        if ((wr >> 1) == r){
            int rl = (wr & 1) * 32;
#pragma unroll
            for (int i = 0; i < 2; i++)
#pragma unroll
            for (int j = 0; j < 4; j++)
                wmma::store_matrix_sync(Cs + (size_t)(rl+i*16)*136 + wc*64 + j*16,
                                        acc[i][j], 136, wmma::mem_row_major);
        }
        __syncthreads();

        int row_l = tid >> 2;
        int n = bm*128 + r*64 + row_l;
        int c0 = (tid & 3) * 32;
        float ws = wsum_buf[n];
        int e0 = eidx[2*n], e1 = eidx[2*n+1];
        float z0[8], z1[8];
#pragma unroll
        for (int q = 0; q < 8; q++){ z0[q] = z2s[n*16+q]; z1[q] = z2s[n*16+8+q]; }
        const float* crow = &Cs[(size_t)row_l*136];
        for (int jj = 0; jj < 32; jj++){
            int col = c0 + jj;
            int d = bn*128 + col;
            float c = crow[col] + ws*b2[d];
            const float4* q0 = (const float4*)&B2[((size_t)e0*D_DIM + d)*R_RANK];
            const float4* q1 = (const float4*)&B2[((size_t)e1*D_DIM + d)*R_RANK];
            float4 u0=q0[0], u1=q0[1], v0=q1[0], v1=q1[1];
            c += z0[0]*u0.x + z0[1]*u0.y + z0[2]*u0.z + z0[3]*u0.w
               + z0[4]*u1.x + z0[5]*u1.y + z0[6]*u1.z + z0[7]*u1.w;
            c += z1[0]*v0.x + z1[1]*v0.y + z1[2]*v0.z + z1[3]*v0.w
               + z1[4]*v1.x + z1[5]*v1.y + z1[6]*v1.z + z1[7]*v1.w;
            out[(size_t)n*D_DIM + d] = c;
        }
    }
}

__global__ __launch_bounds__(256, 2) void fc2_hyb(
    const float* __restrict__ W2, const float* __restrict__ b2,
    const float* __restrict__ B2, float* __restrict__ out)
{
    __shared__ __align__(16) char smem_u[49152];
    int b = blockIdx.x, slot = b & 15, grp = b >> 4;
    if (slot < 9){
        int i = grp * 9 + slot;          // [0,288): 16 N-tiles x 18 token-tiles
        fc2_simt(i / 16, i % 16, smem_u, W2, b2, B2, out);
    } else {
        int j = grp * 7 + (slot - 9);    // [0,224): 16 x 14
        fc2_tens(TSPLIT + j / 16, j % 16, smem_u, W2, b2, B2, out);
    }
}

// ------------------------- launch ------------------------------------------
extern "C" void kernel_launch(void* const* d_in, const int* in_sizes, int n_in,
                              void* d_out, int out_size)
{
    (void)in_sizes; (void)n_in; (void)out_size;
    const float* x  = (const float*)d_in[0];
    const float* Wr = (const float*)d_in[1];
    const float* br = (const float*)d_in[2];
    const float* W1 = (const float*)d_in[3];
    const float* b1 = (const float*)d_in[4];
    const float* W2 = (const float*)d_in[5];
    const float* b2 = (const float*)d_in[6];
    const float* A1 = (const float*)d_in[7];
    const float* B1 = (const float*)d_in[8];
    const float* A2 = (const float*)d_in[9];
    const float* B2 = (const float*)d_in[10];
    float* out = (float*)d_out;

    router_kernel<<<N_TOK, 256>>>(x, Wr, br, A1);
    fc1_hyb<<<2048, 256>>>(x, W1, b1, B1);
    z2_kernel<<<dim3(N_TOK, 2), 256>>>(A2);
    fc2_hyb<<<512, 256>>>(W2, b2, B2, out);
}

// round 15
// speedup vs baseline: 2.2698x; 1.1247x over previous
#include <cuda_runtime.h>
#include <cuda_fp16.h>
#include <mma.h>
#include <math.h>
#include <stdint.h>

using namespace nvcuda;

#define N_TOK 4096
#define D_DIM 2048
#define F_DIM 8192
#define E_EXP 8
#define R_RANK 8
#define SCALING 2.0f

#define BM 128
#define BN 128
#define BK 16
#define TM 8
#define TN 8

// token-tile split: 12 SIMT tiles, 20 tensor tiles (of 32)
#define TSPLIT 12

// tensor smem tile geometry (2-pass: Ah | Al | Bh)
#define TSTRIDE 24
#define TSIZE   (128 * TSTRIDE)
#define STAGE   (3 * TSIZE)          // halves per stage; 2 stages = 36864 B

// ---------------- scratch (~264MB — known-good placement) --------------------
__device__ float  g_buf[(size_t)N_TOK * F_DIM];
__device__ __half h16a[(size_t)N_TOK * F_DIM];
__device__ __half h16b[(size_t)N_TOK * F_DIM];
__device__ float z1c[N_TOK * 16];
__device__ float z2s[N_TOK * 16];
__device__ int   eidx[N_TOK * 2];
__device__ float ew[N_TOK * 2];
__device__ float wsum_buf[N_TOK];

__device__ __forceinline__ float gelu_new(float x) {
    float x3 = x * x * x;
    float t = tanhf(0.7978845608028654f * (x + 0.044715f * x3));
    return 0.5f * x * (1.0f + t);
}
__device__ __forceinline__ uint32_t h2u(__half2 h){ return *(uint32_t*)&h; }
__device__ __forceinline__ uint32_t pkh(float a, float b){
    return h2u(__halves2half2(__float2half_rn(a), __float2half_rn(b)));
}

// ---------------- router — verbatim R1 ---------------------------------------
__global__ __launch_bounds__(256) void router_kernel(
    const float* __restrict__ x, const float* __restrict__ Wr,
    const float* __restrict__ br, const float* __restrict__ A1)
{
    int n = blockIdx.x;
    int tid = threadIdx.x;
    __shared__ float xs[D_DIM];
    __shared__ float red[16][8];
    __shared__ int s_idx[2];

    for (int d = tid; d < D_DIM; d += 256) xs[d] = x[(size_t)n * D_DIM + d];
    __syncthreads();

    float acc[E_EXP];
#pragma unroll
    for (int e = 0; e < E_EXP; e++) acc[e] = 0.f;
    for (int d = tid; d < D_DIM; d += 256) {
        float xv = xs[d];
#pragma unroll
        for (int e = 0; e < E_EXP; e++) acc[e] += xv * Wr[e * D_DIM + d];
    }
#pragma unroll
    for (int e = 0; e < E_EXP; e++) {
        float v = acc[e];
        for (int o = 16; o > 0; o >>= 1) v += __shfl_down_sync(0xffffffffu, v, o);
        if ((tid & 31) == 0) red[e][tid >> 5] = v;
    }
    __syncthreads();

    if (tid == 0) {
        float lg[E_EXP];
#pragma unroll
        for (int e = 0; e < E_EXP; e++) {
            float v = 0.f;
#pragma unroll
            for (int w = 0; w < 8; w++) v += red[e][w];
            lg[e] = v + br[e];
        }
        float mx = lg[0];
#pragma unroll
        for (int e = 1; e < E_EXP; e++) mx = fmaxf(mx, lg[e]);
        float p[E_EXP], se = 0.f;
#pragma unroll
        for (int e = 0; e < E_EXP; e++) { p[e] = expf(lg[e] - mx); se += p[e]; }
        float inv = 1.0f / se;
#pragma unroll
        for (int e = 0; e < E_EXP; e++) p[e] *= inv;
        int i0 = 0;
#pragma unroll
        for (int e = 1; e < E_EXP; e++) if (p[e] > p[i0]) i0 = e;
        int i1 = -1;
#pragma unroll
        for (int e = 0; e < E_EXP; e++) {
            if (e == i0) continue;
            if (i1 < 0 || p[e] > p[i1]) i1 = e;
        }
        s_idx[0] = i0; s_idx[1] = i1;
        eidx[2 * n] = i0; eidx[2 * n + 1] = i1;
        ew[2 * n] = p[i0]; ew[2 * n + 1] = p[i1];
        wsum_buf[n] = p[i0] + p[i1];
    }
    __syncthreads();

    int e0 = s_idx[0], e1 = s_idx[1];
    float u[16];
#pragma unroll
    for (int i = 0; i < 16; i++) u[i] = 0.f;
    for (int d = tid; d < D_DIM; d += 256) {
        float xv = xs[d];
#pragma unroll
        for (int r = 0; r < R_RANK; r++) {
            u[r]     += xv * A1[((size_t)e0 * R_RANK + r) * D_DIM + d];
            u[8 + r] += xv * A1[((size_t)e1 * R_RANK + r) * D_DIM + d];
        }
    }
    __syncthreads();
#pragma unroll
    for (int i = 0; i < 16; i++) {
        float v = u[i];
        for (int o = 16; o > 0; o >>= 1) v += __shfl_down_sync(0xffffffffu, v, o);
        if ((tid & 31) == 0) red[i][tid >> 5] = v;
    }
    __syncthreads();
    if (tid < 16) {
        float v = 0.f;
#pragma unroll
        for (int w = 0; w < 8; w++) v += red[tid][w];
        z1c[n * 16 + tid] = v * SCALING;
    }
}

// ============================================================================
// tensor machinery: fp16 2-pass GEMM (A hi/lo x B hi), on-the-fly conversion
// ============================================================================
typedef wmma::fragment<wmma::matrix_a, 16,16,16, __half, wmma::row_major> HA;
typedef wmma::fragment<wmma::matrix_b, 16,16,16, __half, wmma::col_major> HB;
typedef wmma::fragment<wmma::accumulator, 16,16,16, float> HC;

__device__ __forceinline__ void cvt_store8(__half* base, int so, float4 v0, float4 v1){
    __half2 h0 = __halves2half2(__float2half_rn(v0.x), __float2half_rn(v0.y));
    __half2 h1 = __halves2half2(__float2half_rn(v0.z), __float2half_rn(v0.w));
    __half2 h2 = __halves2half2(__float2half_rn(v1.x), __float2half_rn(v1.y));
    __half2 h3 = __halves2half2(__float2half_rn(v1.z), __float2half_rn(v1.w));
    float2 f0 = __half22float2(h0), f1 = __half22float2(h1);
    float2 f2 = __half22float2(h2), f3 = __half22float2(h3);
    __half2 l0 = __halves2half2(__float2half_rn(v0.x - f0.x), __float2half_rn(v0.y - f0.y));
    __half2 l1 = __halves2half2(__float2half_rn(v0.z - f1.x), __float2half_rn(v0.w - f1.y));
    __half2 l2 = __halves2half2(__float2half_rn(v1.x - f2.x), __float2half_rn(v1.y - f2.y));
    __half2 l3 = __halves2half2(__float2half_rn(v1.z - f3.x), __float2half_rn(v1.w - f3.y));
    *(uint4*)(base + so)         = make_uint4(h2u(h0), h2u(h1), h2u(h2), h2u(h3));
    *(uint4*)(base + TSIZE + so) = make_uint4(h2u(l0), h2u(l1), h2u(l2), h2u(l3));
}
__device__ __forceinline__ void cvt_store8h(__half* base, int so, float4 v0, float4 v1){
    *(uint4*)(base + so) = make_uint4(pkh(v0.x, v0.y), pkh(v0.z, v0.w),
                                      pkh(v1.x, v1.y), pkh(v1.z, v1.w));
}

__device__ __forceinline__ void gemm16cv(
    HC (&acc)[2][4],
    const float* Af, const float* Bf, int K, __half* sm)
{
    const int tid = threadIdx.x, wid = tid >> 5;
    const int wr = wid & 3, wc = wid >> 2;
    const int row = tid >> 1, hf = (tid & 1) * 8;
    const int so = row * TSTRIDE + hf;
#pragma unroll
    for (int i = 0; i < 2; i++)
#pragma unroll
    for (int j = 0; j < 4; j++) wmma::fill_fragment(acc[i][j], 0.f);

    const float* ap = Af + (size_t)row * K + hf;
    const float* bp = Bf + (size_t)row * K + hf;
    float4 a0 = *(const float4*)ap, a1 = *(const float4*)(ap + 4);
    float4 b0 = *(const float4*)bp, b1 = *(const float4*)(bp + 4);
    cvt_store8(sm, so, a0, a1);
    cvt_store8h(sm + 2*TSIZE, so, b0, b1);
    __syncthreads();

    const int nch = K / 16;
    for (int c = 0; c < nch; c++){
        if (c + 1 < nch){
            a0 = *(const float4*)(ap + (c+1)*16);
            a1 = *(const float4*)(ap + (c+1)*16 + 4);
            b0 = *(const float4*)(bp + (c+1)*16);
            b1 = *(const float4*)(bp + (c+1)*16 + 4);
        }
        const __half* st = sm + (c & 1) * STAGE;
        HA ah[2], al[2];
#pragma unroll
        for (int i = 0; i < 2; i++){
            wmma::load_matrix_sync(ah[i], st + (wr*32 + i*16)*TSTRIDE, TSTRIDE);
            wmma::load_matrix_sync(al[i], st + TSIZE + (wr*32 + i*16)*TSTRIDE, TSTRIDE);
        }
#pragma unroll
        for (int j = 0; j < 4; j++){
            HB bh;
            wmma::load_matrix_sync(bh, st + 2*TSIZE + (wc*64 + j*16)*TSTRIDE, TSTRIDE);
#pragma unroll
            for (int i = 0; i < 2; i++){
                wmma::mma_sync(acc[i][j], ah[i], bh, acc[i][j]);
                wmma::mma_sync(acc[i][j], al[i], bh, acc[i][j]);
            }
        }
        if (c + 1 < nch){
            __half* d = sm + ((c + 1) & 1) * STAGE;
            cvt_store8(d, so, a0, a1);
            cvt_store8h(d + 2*TSIZE, so, b0, b1);
        }
        __syncthreads();
    }
}

// ============================================================================
// fc1 hybrid kernel
// ============================================================================
__device__ void fc1_simt(int bm, int bn, char* smem_u,
    const float* __restrict__ A, const float* __restrict__ B,
    const float* __restrict__ b1, const float* __restrict__ B1)
{
    const int K = D_DIM;
    int tid = threadIdx.x;
    float* As = (float*)smem_u;                 // [16][132]
    float* Bs = As + 16 * 132;                  // [16][132]
    float acc[TM][TN];
#pragma unroll
    for (int i = 0; i < TM; i++)
#pragma unroll
        for (int j = 0; j < TN; j++) acc[i][j] = 0.f;

    int tx = tid % 16, ty = tid / 16;
    const float* Ab = A + (size_t)bm * BM * K;
    const float* Bb = B + (size_t)bn * BN * K;
    int rowL = tid >> 2;
    int colL = (tid & 3) * 4;

    for (int k0 = 0; k0 < K; k0 += BK) {
#pragma unroll
        for (int i = 0; i < 2; i++) {
            float4 a = *(const float4*)(Ab + (size_t)(rowL + i * 64) * K + k0 + colL);
            As[(colL + 0) * 132 + rowL + i * 64] = a.x;
            As[(colL + 1) * 132 + rowL + i * 64] = a.y;
            As[(colL + 2) * 132 + rowL + i * 64] = a.z;
            As[(colL + 3) * 132 + rowL + i * 64] = a.w;
            float4 b = *(const float4*)(Bb + (size_t)(rowL + i * 64) * K + k0 + colL);
            Bs[(colL + 0) * 132 + rowL + i * 64] = b.x;
            Bs[(colL + 1) * 132 + rowL + i * 64] = b.y;
            Bs[(colL + 2) * 132 + rowL + i * 64] = b.z;
            Bs[(colL + 3) * 132 + rowL + i * 64] = b.w;
        }
        __syncthreads();
#pragma unroll
        for (int kk = 0; kk < BK; kk++) {
            float4 a0 = *(const float4*)&As[kk * 132 + ty * TM];
            float4 a1 = *(const float4*)&As[kk * 132 + ty * TM + 4];
            float4 b0 = *(const float4*)&Bs[kk * 132 + tx * TN];
            float4 b1v = *(const float4*)&Bs[kk * 132 + tx * TN + 4];
            float ra[8] = {a0.x, a0.y, a0.z, a0.w, a1.x, a1.y, a1.z, a1.w};
            float rb[8] = {b0.x, b0.y, b0.z, b0.w, b1v.x, b1v.y, b1v.z, b1v.w};
#pragma unroll
            for (int i = 0; i < TM; i++)
#pragma unroll
                for (int j = 0; j < TN; j++) acc[i][j] += ra[i] * rb[j];
        }
        __syncthreads();
    }

    int nrow0 = bm * BM + ty * TM;
    int fcol0 = bn * BN + tx * TN;
#pragma unroll
    for (int i = 0; i < TM; i++) {
        int n = nrow0 + i;
        int e0 = eidx[2 * n], e1 = eidx[2 * n + 1];
        float w0 = ew[2 * n], w1 = ew[2 * n + 1];
        const float4* zp = (const float4*)&z1c[n * 16];
        float4 z0a = zp[0], z0b = zp[1], z1a = zp[2], z1b = zp[3];
        float h0v[TN], h1v[TN], gv[TN];
#pragma unroll
        for (int j = 0; j < TN; j++) {
            int f = fcol0 + j;
            float c = acc[i][j] + b1[f];
            const float4* q0 = (const float4*)&B1[((size_t)e0 * F_DIM + f) * R_RANK];
            float4 u0 = q0[0], u1 = q0[1];
            float l0 = z0a.x * u0.x + z0a.y * u0.y + z0a.z * u0.z + z0a.w * u0.w
                     + z0b.x * u1.x + z0b.y * u1.y + z0b.z * u1.z + z0b.w * u1.w;
            const float4* q1 = (const float4*)&B1[((size_t)e1 * F_DIM + f) * R_RANK];
            float4 v0 = q1[0], v1 = q1[1];
            float l1 = z1a.x * v0.x + z1a.y * v0.y + z1a.z * v0.z + z1a.w * v0.w
                     + z1b.x * v1.x + z1b.y * v1.y + z1b.z * v1.z + z1b.w * v1.w;
            float h0 = gelu_new(c + l0);
            float h1 = gelu_new(c + l1);
            h0v[j] = h0; h1v[j] = h1;
            gv[j] = w0 * h0 + w1 * h1;
        }
        size_t off = (size_t)n * F_DIM + fcol0;
        *(uint4*)&h16a[off] = make_uint4(pkh(h0v[0],h0v[1]), pkh(h0v[2],h0v[3]),
                                         pkh(h0v[4],h0v[5]), pkh(h0v[6],h0v[7]));
        *(uint4*)&h16b[off] = make_uint4(pkh(h1v[0],h1v[1]), pkh(h1v[2],h1v[3]),
                                         pkh(h1v[4],h1v[5]), pkh(h1v[6],h1v[7]));
        *(float4*)&g_buf[off]     = make_float4(gv[0], gv[1], gv[2], gv[3]);
        *(float4*)&g_buf[off + 4] = make_float4(gv[4], gv[5], gv[6], gv[7]);
    }
}

__device__ void fc1_tens(int bm, int bn, char* smem_u,
    const float* __restrict__ x, const float* __restrict__ W1,
    const float* __restrict__ b1, const float* __restrict__ B1)
{
    __half* smh = (__half*)smem_u;
    int tid = threadIdx.x, wid = tid >> 5, wr = wid & 3, wc = wid >> 2;
    HC acc[2][4];
    gemm16cv(acc, x + (size_t)bm*128*D_DIM, W1 + (size_t)bn*128*D_DIM, D_DIM, smh);

    float* Cs = (float*)smem_u;   // 64 x 136 floats = 34816 B (fits 36864)
    for (int r = 0; r < 2; r++){
        __syncthreads();
        if ((wr >> 1) == r){
            int rl = (wr & 1) * 32;
#pragma unroll
            for (int i = 0; i < 2; i++)
#pragma unroll
            for (int j = 0; j < 4; j++)
                wmma::store_matrix_sync(Cs + (size_t)(rl+i*16)*136 + wc*64 + j*16,
                                        acc[i][j], 136, wmma::mem_row_major);
        }
        __syncthreads();

        int row_l = tid >> 2;
        int n = bm*128 + r*64 + row_l;
        int c0 = (tid & 3) * 32;
        int e0 = eidx[2*n], e1 = eidx[2*n+1];
        float w0 = ew[2*n], w1w = ew[2*n+1];
        float z0[8], z1[8];
#pragma unroll
        for (int q = 0; q < 8; q++){ z0[q] = z1c[n*16+q]; z1[q] = z1c[n*16+8+q]; }
        const float* crow = &Cs[(size_t)row_l*136];
        for (int jj = 0; jj < 32; jj += 2){
            int col = c0 + jj;
            int f = bn*128 + col;
            float ca = crow[col]   + b1[f];
            float cb = crow[col+1] + b1[f+1];
            const float4* q0 = (const float4*)&B1[((size_t)e0*F_DIM + f)*R_RANK];
            const float4* q1 = (const float4*)&B1[((size_t)e1*F_DIM + f)*R_RANK];
            float l0a=0.f, l0b=0.f, l1a=0.f, l1b=0.f;
#pragma unroll
            for (int q = 0; q < 2; q++){
                float4 u0=q0[q], u2=q0[2+q], v0=q1[q], v2=q1[2+q];
                l0a += z0[q*4+0]*u0.x + z0[q*4+1]*u0.y + z0[q*4+2]*u0.z + z0[q*4+3]*u0.w;
                l0b += z0[q*4+0]*u2.x + z0[q*4+1]*u2.y + z0[q*4+2]*u2.z + z0[q*4+3]*u2.w;
                l1a += z1[q*4+0]*v0.x + z1[q*4+1]*v0.y + z1[q*4+2]*v0.z + z1[q*4+3]*v0.w;
                l1b += z1[q*4+0]*v2.x + z1[q*4+1]*v2.y + z1[q*4+2]*v2.z + z1[q*4+3]*v2.w;
            }
            float h0a = gelu_new(ca + l0a), h0b_ = gelu_new(cb + l0b);
            float h1a = gelu_new(ca + l1a), h1b_ = gelu_new(cb + l1b);
            size_t off = (size_t)n*F_DIM + f;
            *(uint32_t*)&h16a[off] = pkh(h0a, h0b_);
            *(uint32_t*)&h16b[off] = pkh(h1a, h1b_);
            *(float2*)&g_buf[off] = make_float2(w0*h0a + w1w*h1a, w0*h0b_ + w1w*h1b_);
        }
    }
}

__global__ __launch_bounds__(256, 2) void fc1_hyb(
    const float* __restrict__ x, const float* __restrict__ W1,
    const float* __restrict__ b1, const float* __restrict__ B1)
{
    __shared__ __align__(16) char smem_u[36864];
    int b = blockIdx.x, slot = b & 15, grp = b >> 4;   // grp in [0,128)
    if (slot < 6){
        int i = grp * 6 + slot;          // [0,768) = 12 x 64
        fc1_simt(i / 64, i % 64, smem_u, x, W1, b1, B1);
    } else {
        int j = grp * 10 + (slot - 6);   // [0,1280) = 20 x 64
        fc1_tens(TSPLIT + j / 64, j % 64, smem_u, x, W1, b1, B1);
    }
}

// ============================================================================
// z2 — R13-verified (reads fp16 h planes)
// ============================================================================
__global__ __launch_bounds__(256) void z2_kernel(const float* __restrict__ A2)
{
    int n = blockIdx.x;
    int k = blockIdx.y;
    int tid = threadIdx.x;
    int e = eidx[2 * n + k];
    const __half* h = (k ? h16b : h16a) + (size_t)n * F_DIM;
    const float* a2 = A2 + (size_t)e * R_RANK * F_DIM;

    float acc[R_RANK];
#pragma unroll
    for (int r = 0; r < R_RANK; r++) acc[r] = 0.f;

    for (int f = tid * 4; f < F_DIM; f += 1024) {
        uint2 hp = *(const uint2*)(h + f);
        float2 f0 = __half22float2(*(__half2*)&hp.x);
        float2 f1 = __half22float2(*(__half2*)&hp.y);
#pragma unroll
        for (int r = 0; r < R_RANK; r++) {
            float4 av = *(const float4*)(a2 + (size_t)r * F_DIM + f);
            acc[r] += f0.x * av.x + f0.y * av.y + f1.x * av.z + f1.y * av.w;
        }
    }
    __shared__ float red[R_RANK][8];
#pragma unroll
    for (int r = 0; r < R_RANK; r++) {
        float v = acc[r];
        for (int o = 16; o > 0; o >>= 1) v += __shfl_down_sync(0xffffffffu, v, o);
        if ((tid & 31) == 0) red[r][tid >> 5] = v;
    }
    __syncthreads();
    if (tid < R_RANK) {
        float v = 0.f;
#pragma unroll
        for (int w = 0; w < 8; w++) v += red[tid][w];
        z2s[n * 16 + k * 8 + tid] = v * SCALING * ew[2 * n + k];
    }
}

// ============================================================================
// fc2 hybrid kernel
// ============================================================================
__device__ void fc2_simt(int bm, int bn, char* smem_u,
    const float* __restrict__ B, const float* __restrict__ b2,
    const float* __restrict__ B2, float* __restrict__ out)
{
    const int K = F_DIM;
    int tid = threadIdx.x;
    float* As = (float*)smem_u;
    float* Bs = As + 16 * 132;
    float acc[TM][TN];
#pragma unroll
    for (int i = 0; i < TM; i++)
#pragma unroll
        for (int j = 0; j < TN; j++) acc[i][j] = 0.f;

    int tx = tid % 16, ty = tid / 16;
    const float* Ab = g_buf + (size_t)bm * BM * K;
    const float* Bb = B + (size_t)bn * BN * K;
    int rowL = tid >> 2;
    int colL = (tid & 3) * 4;

    for (int k0 = 0; k0 < K; k0 += BK) {
#pragma unroll
        for (int i = 0; i < 2; i++) {
            float4 a = *(const float4*)(Ab + (size_t)(rowL + i * 64) * K + k0 + colL);
            As[(colL + 0) * 132 + rowL + i * 64] = a.x;
            As[(colL + 1) * 132 + rowL + i * 64] = a.y;
            As[(colL + 2) * 132 + rowL + i * 64] = a.z;
            As[(colL + 3) * 132 + rowL + i * 64] = a.w;
            float4 b = *(const float4*)(Bb + (size_t)(rowL + i * 64) * K + k0 + colL);
            Bs[(colL + 0) * 132 + rowL + i * 64] = b.x;
            Bs[(colL + 1) * 132 + rowL + i * 64] = b.y;
            Bs[(colL + 2) * 132 + rowL + i * 64] = b.z;
            Bs[(colL + 3) * 132 + rowL + i * 64] = b.w;
        }
        __syncthreads();
#pragma unroll
        for (int kk = 0; kk < BK; kk++) {
            float4 a0 = *(const float4*)&As[kk * 132 + ty * TM];
            float4 a1 = *(const float4*)&As[kk * 132 + ty * TM + 4];
            float4 b0 = *(const float4*)&Bs[kk * 132 + tx * TN];
            float4 b1v = *(const float4*)&Bs[kk * 132 + tx * TN + 4];
            float ra[8] = {a0.x, a0.y, a0.z, a0.w, a1.x, a1.y, a1.z, a1.w};
            float rb[8] = {b0.x, b0.y, b0.z, b0.w, b1v.x, b1v.y, b1v.z, b1v.w};
#pragma unroll
            for (int i = 0; i < TM; i++)
#pragma unroll
                for (int j = 0; j < TN; j++) acc[i][j] += ra[i] * rb[j];
        }
        __syncthreads();
    }

    int nrow0 = bm * BM + ty * TM;
    int dcol0 = bn * BN + tx * TN;
#pragma unroll
    for (int i = 0; i < TM; i++) {
        int n = nrow0 + i;
        float ws = wsum_buf[n];
        int e0 = eidx[2 * n], e1 = eidx[2 * n + 1];
        const float4* zp = (const float4*)&z2s[n * 16];
        float4 z0a = zp[0], z0b = zp[1], z1a = zp[2], z1b = zp[3];
        float ov[TN];
#pragma unroll
        for (int j = 0; j < TN; j++) {
            int d = dcol0 + j;
            float c = acc[i][j] + ws * b2[d];
            const float4* q0 = (const float4*)&B2[((size_t)e0 * D_DIM + d) * R_RANK];
            float4 u0 = q0[0], u1 = q0[1];
            c += z0a.x * u0.x + z0a.y * u0.y + z0a.z * u0.z + z0a.w * u0.w
               + z0b.x * u1.x + z0b.y * u1.y + z0b.z * u1.z + z0b.w * u1.w;
            const float4* q1 = (const float4*)&B2[((size_t)e1 * D_DIM + d) * R_RANK];
            float4 v0 = q1[0], v1 = q1[1];
            c += z1a.x * v0.x + z1a.y * v0.y + z1a.z * v0.z + z1a.w * v0.w
               + z1b.x * v1.x + z1b.y * v1.y + z1b.z * v1.z + z1b.w * v1.w;
            ov[j] = c;
        }
        size_t off = (size_t)n * D_DIM + dcol0;
        *(float4*)&out[off]     = make_float4(ov[0], ov[1], ov[2], ov[3]);
        *(float4*)&out[off + 4] = make_float4(ov[4], ov[5], ov[6], ov[7]);
    }
}

__device__ void fc2_tens(int bm, int bn, char* smem_u,
    const float* __restrict__ W2, const float* __restrict__ b2,
    const float* __restrict__ B2, float* __restrict__ out)
{
    __half* smh = (__half*)smem_u;
    int tid = threadIdx.x, wid = tid >> 5, wr = wid & 3, wc = wid >> 2;
    HC acc[2][4];
    gemm16cv(acc, g_buf + (size_t)bm*128*F_DIM, W2 + (size_t)bn*128*F_DIM, F_DIM, smh);

    float* Cs = (float*)smem_u;
    for (int r = 0; r < 2; r++){
        __syncthreads();
        if ((wr >> 1) == r){
            int rl = (wr & 1) * 32;
#pragma unroll
            for (int i = 0; i < 2; i++)
#pragma unroll
            for (int j = 0; j < 4; j++)
                wmma::store_matrix_sync(Cs + (size_t)(rl+i*16)*136 + wc*64 + j*16,
                                        acc[i][j], 136, wmma::mem_row_major);
        }
        __syncthreads();

        int row_l = tid >> 2;
        int n = bm*128 + r*64 + row_l;
        int c0 = (tid & 3) * 32;
        float ws = wsum_buf[n];
        int e0 = eidx[2*n], e1 = eidx[2*n+1];
        float z0[8], z1[8];
#pragma unroll
        for (int q = 0; q < 8; q++){ z0[q] = z2s[n*16+q]; z1[q] = z2s[n*16+8+q]; }
        const float* crow = &Cs[(size_t)row_l*136];
        for (int jj = 0; jj < 32; jj++){
            int col = c0 + jj;
            int d = bn*128 + col;
            float c = crow[col] + ws*b2[d];
            const float4* q0 = (const float4*)&B2[((size_t)e0*D_DIM + d)*R_RANK];
            const float4* q1 = (const float4*)&B2[((size_t)e1*D_DIM + d)*R_RANK];
            float4 u0=q0[0], u1=q0[1], v0=q1[0], v1=q1[1];
            c += z0[0]*u0.x + z0[1]*u0.y + z0[2]*u0.z + z0[3]*u0.w
               + z0[4]*u1.x + z0[5]*u1.y + z0[6]*u1.z + z0[7]*u1.w;
            c += z1[0]*v0.x + z1[1]*v0.y + z1[2]*v0.z + z1[3]*v0.w
               + z1[4]*v1.x + z1[5]*v1.y + z1[6]*v1.z + z1[7]*v1.w;
            out[(size_t)n*D_DIM + d] = c;
        }
    }
}

__global__ __launch_bounds__(256, 2) void fc2_hyb(
    const float* __restrict__ W2, const float* __restrict__ b2,
    const float* __restrict__ B2, float* __restrict__ out)
{
    __shared__ __align__(16) char smem_u[36864];
    int b = blockIdx.x, slot = b & 15, grp = b >> 4;   // grp in [0,32)
    if (slot < 6){
        int i = grp * 6 + slot;          // [0,192) = 12 x 16
        fc2_simt(i / 16, i % 16, smem_u, W2, b2, B2, out);
    } else {
        int j = grp * 10 + (slot - 6);   // [0,320) = 20 x 16
        fc2_tens(TSPLIT + j / 16, j % 16, smem_u, W2, b2, B2, out);
    }
}

// ------------------------- launch ------------------------------------------
extern "C" void kernel_launch(void* const* d_in, const int* in_sizes, int n_in,
                              void* d_out, int out_size)
{
    (void)in_sizes; (void)n_in; (void)out_size;
    const float* x  = (const float*)d_in[0];
    const float* Wr = (const float*)d_in[1];
    const float* br = (const float*)d_in[2];
    const float* W1 = (const float*)d_in[3];
    const float* b1 = (const float*)d_in[4];
    const float* W2 = (const float*)d_in[5];
    const float* b2 = (const float*)d_in[6];
    const float* A1 = (const float*)d_in[7];
    const float* B1 = (const float*)d_in[8];
    const float* A2 = (const float*)d_in[9];
    const float* B2 = (const float*)d_in[10];
    float* out = (float*)d_out;

    router_kernel<<<N_TOK, 256>>>(x, Wr, br, A1);
    fc1_hyb<<<2048, 256>>>(x, W1, b1, B1);
    z2_kernel<<<dim3(N_TOK, 2), 256>>>(A2);
    fc2_hyb<<<512, 256>>>(W2, b2, B2, out);
}

// round 16
// speedup vs baseline: 2.6078x; 1.1489x over previous
#include <cuda_runtime.h>
#include <cuda_fp16.h>
#include <mma.h>
#include <math.h>
#include <stdint.h>

using namespace nvcuda;

#define N_TOK 4096
#define D_DIM 2048
#define F_DIM 8192
#define E_EXP 8
#define R_RANK 8
#define SCALING 2.0f

#define BM 128
#define BN 128
#define BK 16
#define TM 8
#define TN 8

// token-tile split: 10 SIMT tiles, 22 tensor tiles (of 32)
#define TSPLIT 10

// tensor smem tile geometry (1-pass: Ah | Bh)
#define TSTRIDE 24
#define TSIZE   (128 * TSTRIDE)
#define STAGE   (2 * TSIZE)          // halves per stage; 2 stages = 24576 B

// ---------------- scratch (~264MB — known-good placement) --------------------
__device__ float  g_buf[(size_t)N_TOK * F_DIM];
__device__ __half h16a[(size_t)N_TOK * F_DIM];
__device__ __half h16b[(size_t)N_TOK * F_DIM];
__device__ float z1c[N_TOK * 16];
__device__ float z2s[N_TOK * 16];
__device__ int   eidx[N_TOK * 2];
__device__ float ew[N_TOK * 2];
__device__ float wsum_buf[N_TOK];

__device__ __forceinline__ float gelu_new(float x) {
    float x3 = x * x * x;
    float t = tanhf(0.7978845608028654f * (x + 0.044715f * x3));
    return 0.5f * x * (1.0f + t);
}
__device__ __forceinline__ uint32_t h2u(__half2 h){ return *(uint32_t*)&h; }
__device__ __forceinline__ uint32_t pkh(float a, float b){
    return h2u(__halves2half2(__float2half_rn(a), __float2half_rn(b)));
}

// ---------------- router — verbatim R1 ---------------------------------------
__global__ __launch_bounds__(256) void router_kernel(
    const float* __restrict__ x, const float* __restrict__ Wr,
    const float* __restrict__ br, const float* __restrict__ A1)
{
    int n = blockIdx.x;
    int tid = threadIdx.x;
    __shared__ float xs[D_DIM];
    __shared__ float red[16][8];
    __shared__ int s_idx[2];

    for (int d = tid; d < D_DIM; d += 256) xs[d] = x[(size_t)n * D_DIM + d];
    __syncthreads();

    float acc[E_EXP];
#pragma unroll
    for (int e = 0; e < E_EXP; e++) acc[e] = 0.f;
    for (int d = tid; d < D_DIM; d += 256) {
        float xv = xs[d];
#pragma unroll
        for (int e = 0; e < E_EXP; e++) acc[e] += xv * Wr[e * D_DIM + d];
    }
#pragma unroll
    for (int e = 0; e < E_EXP; e++) {
        float v = acc[e];
        for (int o = 16; o > 0; o >>= 1) v += __shfl_down_sync(0xffffffffu, v, o);
        if ((tid & 31) == 0) red[e][tid >> 5] = v;
    }
    __syncthreads();

    if (tid == 0) {
        float lg[E_EXP];
#pragma unroll
        for (int e = 0; e < E_EXP; e++) {
            float v = 0.f;
#pragma unroll
            for (int w = 0; w < 8; w++) v += red[e][w];
            lg[e] = v + br[e];
        }
        float mx = lg[0];
#pragma unroll
        for (int e = 1; e < E_EXP; e++) mx = fmaxf(mx, lg[e]);
        float p[E_EXP], se = 0.f;
#pragma unroll
        for (int e = 0; e < E_EXP; e++) { p[e] = expf(lg[e] - mx); se += p[e]; }
        float inv = 1.0f / se;
#pragma unroll
        for (int e = 0; e < E_EXP; e++) p[e] *= inv;
        int i0 = 0;
#pragma unroll
        for (int e = 1; e < E_EXP; e++) if (p[e] > p[i0]) i0 = e;
        int i1 = -1;
#pragma unroll
        for (int e = 0; e < E_EXP; e++) {
            if (e == i0) continue;
            if (i1 < 0 || p[e] > p[i1]) i1 = e;
        }
        s_idx[0] = i0; s_idx[1] = i1;
        eidx[2 * n] = i0; eidx[2 * n + 1] = i1;
        ew[2 * n] = p[i0]; ew[2 * n + 1] = p[i1];
        wsum_buf[n] = p[i0] + p[i1];
    }
    __syncthreads();

    int e0 = s_idx[0], e1 = s_idx[1];
    float u[16];
#pragma unroll
    for (int i = 0; i < 16; i++) u[i] = 0.f;
    for (int d = tid; d < D_DIM; d += 256) {
        float xv = xs[d];
#pragma unroll
        for (int r = 0; r < R_RANK; r++) {
            u[r]     += xv * A1[((size_t)e0 * R_RANK + r) * D_DIM + d];
            u[8 + r] += xv * A1[((size_t)e1 * R_RANK + r) * D_DIM + d];
        }
    }
    __syncthreads();
#pragma unroll
    for (int i = 0; i < 16; i++) {
        float v = u[i];
        for (int o = 16; o > 0; o >>= 1) v += __shfl_down_sync(0xffffffffu, v, o);
        if ((tid & 31) == 0) red[i][tid >> 5] = v;
    }
    __syncthreads();
    if (tid < 16) {
        float v = 0.f;
#pragma unroll
        for (int w = 0; w < 8; w++) v += red[tid][w];
        z1c[n * 16 + tid] = v * SCALING;
    }
}

// ============================================================================
// tensor machinery: fp16 1-pass GEMM (Ah x Bh), on-the-fly conversion
// ============================================================================
typedef wmma::fragment<wmma::matrix_a, 16,16,16, __half, wmma::row_major> HA;
typedef wmma::fragment<wmma::matrix_b, 16,16,16, __half, wmma::col_major> HB;
typedef wmma::fragment<wmma::accumulator, 16,16,16, float> HC;

__device__ __forceinline__ void cvt_store8h(__half* base, int so, float4 v0, float4 v1){
    *(uint4*)(base + so) = make_uint4(pkh(v0.x, v0.y), pkh(v0.z, v0.w),
                                      pkh(v1.x, v1.y), pkh(v1.z, v1.w));
}

__device__ __forceinline__ void gemm16cv(
    HC (&acc)[2][4],
    const float* Af, const float* Bf, int K, __half* sm)
{
    const int tid = threadIdx.x, wid = tid >> 5;
    const int wr = wid & 3, wc = wid >> 2;
    const int row = tid >> 1, hf = (tid & 1) * 8;
    const int so = row * TSTRIDE + hf;
#pragma unroll
    for (int i = 0; i < 2; i++)
#pragma unroll
    for (int j = 0; j < 4; j++) wmma::fill_fragment(acc[i][j], 0.f);

    const float* ap = Af + (size_t)row * K + hf;
    const float* bp = Bf + (size_t)row * K + hf;
    float4 a0 = *(const float4*)ap, a1 = *(const float4*)(ap + 4);
    float4 b0 = *(const float4*)bp, b1 = *(const float4*)(bp + 4);
    cvt_store8h(sm, so, a0, a1);
    cvt_store8h(sm + TSIZE, so, b0, b1);
    __syncthreads();

    const int nch = K / 16;
    for (int c = 0; c < nch; c++){
        if (c + 1 < nch){
            a0 = *(const float4*)(ap + (c+1)*16);
            a1 = *(const float4*)(ap + (c+1)*16 + 4);
            b0 = *(const float4*)(bp + (c+1)*16);
            b1 = *(const float4*)(bp + (c+1)*16 + 4);
        }
        const __half* st = sm + (c & 1) * STAGE;
        HA ah[2];
#pragma unroll
        for (int i = 0; i < 2; i++)
            wmma::load_matrix_sync(ah[i], st + (wr*32 + i*16)*TSTRIDE, TSTRIDE);
#pragma unroll
        for (int j = 0; j < 4; j++){
            HB bh;
            wmma::load_matrix_sync(bh, st + TSIZE + (wc*64 + j*16)*TSTRIDE, TSTRIDE);
#pragma unroll
            for (int i = 0; i < 2; i++)
                wmma::mma_sync(acc[i][j], ah[i], bh, acc[i][j]);
        }
        if (c + 1 < nch){
            __half* d = sm + ((c + 1) & 1) * STAGE;
            cvt_store8h(d, so, a0, a1);
            cvt_store8h(d + TSIZE, so, b0, b1);
        }
        __syncthreads();
    }
}

// ============================================================================
// fc1 hybrid kernel
// ============================================================================
__device__ void fc1_simt(int bm, int bn, char* smem_u,
    const float* __restrict__ A, const float* __restrict__ B,
    const float* __restrict__ b1, const float* __restrict__ B1)
{
    const int K = D_DIM;
    int tid = threadIdx.x;
    float* As = (float*)smem_u;                 // [16][132]
    float* Bs = As + 16 * 132;                  // [16][132]
    float acc[TM][TN];
#pragma unroll
    for (int i = 0; i < TM; i++)
#pragma unroll
        for (int j = 0; j < TN; j++) acc[i][j] = 0.f;

    int tx = tid % 16, ty = tid / 16;
    const float* Ab = A + (size_t)bm * BM * K;
    const float* Bb = B + (size_t)bn * BN * K;
    int rowL = tid >> 2;
    int colL = (tid & 3) * 4;

    for (int k0 = 0; k0 < K; k0 += BK) {
#pragma unroll
        for (int i = 0; i < 2; i++) {
            float4 a = *(const float4*)(Ab + (size_t)(rowL + i * 64) * K + k0 + colL);
            As[(colL + 0) * 132 + rowL + i * 64] = a.x;
            As[(colL + 1) * 132 + rowL + i * 64] = a.y;
            As[(colL + 2) * 132 + rowL + i * 64] = a.z;
            As[(colL + 3) * 132 + rowL + i * 64] = a.w;
            float4 b = *(const float4*)(Bb + (size_t)(rowL + i * 64) * K + k0 + colL);
            Bs[(colL + 0) * 132 + rowL + i * 64] = b.x;
            Bs[(colL + 1) * 132 + rowL + i * 64] = b.y;
            Bs[(colL + 2) * 132 + rowL + i * 64] = b.z;
            Bs[(colL + 3) * 132 + rowL + i * 64] = b.w;
        }
        __syncthreads();
#pragma unroll
        for (int kk = 0; kk < BK; kk++) {
            float4 a0 = *(const float4*)&As[kk * 132 + ty * TM];
            float4 a1 = *(const float4*)&As[kk * 132 + ty * TM + 4];
            float4 b0 = *(const float4*)&Bs[kk * 132 + tx * TN];
            float4 b1v = *(const float4*)&Bs[kk * 132 + tx * TN + 4];
            float ra[8] = {a0.x, a0.y, a0.z, a0.w, a1.x, a1.y, a1.z, a1.w};
            float rb[8] = {b0.x, b0.y, b0.z, b0.w, b1v.x, b1v.y, b1v.z, b1v.w};
#pragma unroll
            for (int i = 0; i < TM; i++)
#pragma unroll
                for (int j = 0; j < TN; j++) acc[i][j] += ra[i] * rb[j];
        }
        __syncthreads();
    }

    int nrow0 = bm * BM + ty * TM;
    int fcol0 = bn * BN + tx * TN;
#pragma unroll
    for (int i = 0; i < TM; i++) {
        int n = nrow0 + i;
        int e0 = eidx[2 * n], e1 = eidx[2 * n + 1];
        float w0 = ew[2 * n], w1 = ew[2 * n + 1];
        const float4* zp = (const float4*)&z1c[n * 16];
        float4 z0a = zp[0], z0b = zp[1], z1a = zp[2], z1b = zp[3];
        float h0v[TN], h1v[TN], gv[TN];
#pragma unroll
        for (int j = 0; j < TN; j++) {
            int f = fcol0 + j;
            float c = acc[i][j] + b1[f];
            const float4* q0 = (const float4*)&B1[((size_t)e0 * F_DIM + f) * R_RANK];
            float4 u0 = q0[0], u1 = q0[1];
            float l0 = z0a.x * u0.x + z0a.y * u0.y + z0a.z * u0.z + z0a.w * u0.w
                     + z0b.x * u1.x + z0b.y * u1.y + z0b.z * u1.z + z0b.w * u1.w;
            const float4* q1 = (const float4*)&B1[((size_t)e1 * F_DIM + f) * R_RANK];
            float4 v0 = q1[0], v1 = q1[1];
            float l1 = z1a.x * v0.x + z1a.y * v0.y + z1a.z * v0.z + z1a.w * v0.w
                     + z1b.x * v1.x + z1b.y * v1.y + z1b.z * v1.z + z1b.w * v1.w;
            float h0 = gelu_new(c + l0);
            float h1 = gelu_new(c + l1);
            h0v[j] = h0; h1v[j] = h1;
            gv[j] = w0 * h0 + w1 * h1;
        }
        size_t off = (size_t)n * F_DIM + fcol0;
        *(uint4*)&h16a[off] = make_uint4(pkh(h0v[0],h0v[1]), pkh(h0v[2],h0v[3]),
                                         pkh(h0v[4],h0v[5]), pkh(h0v[6],h0v[7]));
        *(uint4*)&h16b[off] = make_uint4(pkh(h1v[0],h1v[1]), pkh(h1v[2],h1v[3]),
                                         pkh(h1v[4],h1v[5]), pkh(h1v[6],h1v[7]));
        *(float4*)&g_buf[off]     = make_float4(gv[0], gv[1], gv[2], gv[3]);
        *(float4*)&g_buf[off + 4] = make_float4(gv[4], gv[5], gv[6], gv[7]);
    }
}

__device__ void fc1_tens(int bm, int bn, char* smem_u,
    const float* __restrict__ x, const float* __restrict__ W1,
    const float* __restrict__ b1, const float* __restrict__ B1)
{
    __half* smh = (__half*)smem_u;
    int tid = threadIdx.x, wid = tid >> 5, wr = wid & 3, wc = wid >> 2;
    HC acc[2][4];
    gemm16cv(acc, x + (size_t)bm*128*D_DIM, W1 + (size_t)bn*128*D_DIM, D_DIM, smh);

    float* Cs = (float*)smem_u;   // 64 x 136 floats = 34816 B (fits 36864)
    for (int r = 0; r < 2; r++){
        __syncthreads();
        if ((wr >> 1) == r){
            int rl = (wr & 1) * 32;
#pragma unroll
            for (int i = 0; i < 2; i++)
#pragma unroll
            for (int j = 0; j < 4; j++)
                wmma::store_matrix_sync(Cs + (size_t)(rl+i*16)*136 + wc*64 + j*16,
                                        acc[i][j], 136, wmma::mem_row_major);
        }
        __syncthreads();

        int row_l = tid >> 2;
        int n = bm*128 + r*64 + row_l;
        int c0 = (tid & 3) * 32;
        int e0 = eidx[2*n], e1 = eidx[2*n+1];
        float w0 = ew[2*n], w1w = ew[2*n+1];
        float z0[8], z1[8];
#pragma unroll
        for (int q = 0; q < 8; q++){ z0[q] = z1c[n*16+q]; z1[q] = z1c[n*16+8+q]; }
        const float* crow = &Cs[(size_t)row_l*136];
        for (int jj = 0; jj < 32; jj += 2){
            int col = c0 + jj;
            int f = bn*128 + col;
            float ca = crow[col]   + b1[f];
            float cb = crow[col+1] + b1[f+1];
            const float4* q0 = (const float4*)&B1[((size_t)e0*F_DIM + f)*R_RANK];
            const float4* q1 = (const float4*)&B1[((size_t)e1*F_DIM + f)*R_RANK];
            float l0a=0.f, l0b=0.f, l1a=0.f, l1b=0.f;
#pragma unroll
            for (int q = 0; q < 2; q++){
                float4 u0=q0[q], u2=q0[2+q], v0=q1[q], v2=q1[2+q];
                l0a += z0[q*4+0]*u0.x + z0[q*4+1]*u0.y + z0[q*4+2]*u0.z + z0[q*4+3]*u0.w;
                l0b += z0[q*4+0]*u2.x + z0[q*4+1]*u2.y + z0[q*4+2]*u2.z + z0[q*4+3]*u2.w;
                l1a += z1[q*4+0]*v0.x + z1[q*4+1]*v0.y + z1[q*4+2]*v0.z + z1[q*4+3]*v0.w;
                l1b += z1[q*4+0]*v2.x + z1[q*4+1]*v2.y + z1[q*4+2]*v2.z + z1[q*4+3]*v2.w;
            }
            float h0a = gelu_new(ca + l0a), h0b_ = gelu_new(cb + l0b);
            float h1a = gelu_new(ca + l1a), h1b_ = gelu_new(cb + l1b);
            size_t off = (size_t)n*F_DIM + f;
            *(uint32_t*)&h16a[off] = pkh(h0a, h0b_);
            *(uint32_t*)&h16b[off] = pkh(h1a, h1b_);
            *(float2*)&g_buf[off] = make_float2(w0*h0a + w1w*h1a, w0*h0b_ + w1w*h1b_);
        }
    }
}

__global__ __launch_bounds__(256, 2) void fc1_hyb(
    const float* __restrict__ x, const float* __restrict__ W1,
    const float* __restrict__ b1, const float* __restrict__ B1)
{
    __shared__ __align__(16) char smem_u[36864];
    int b = blockIdx.x, slot = b & 15, grp = b >> 4;   // grp in [0,128)
    if (slot < 5){
        int i = grp * 5 + slot;          // [0,640) = 10 x 64
        fc1_simt(i / 64, i % 64, smem_u, x, W1, b1, B1);
    } else {
        int j = grp * 11 + (slot - 5);   // [0,1408) = 22 x 64
        fc1_tens(TSPLIT + j / 64, j % 64, smem_u, x, W1, b1, B1);
    }
}

// ============================================================================
// z2 — R13-verified (reads fp16 h planes)
// ============================================================================
__global__ __launch_bounds__(256) void z2_kernel(const float* __restrict__ A2)
{
    int n = blockIdx.x;
    int k = blockIdx.y;
    int tid = threadIdx.x;
    int e = eidx[2 * n + k];
    const __half* h = (k ? h16b : h16a) + (size_t)n * F_DIM;
    const float* a2 = A2 + (size_t)e * R_RANK * F_DIM;

    float acc[R_RANK];
#pragma unroll
    for (int r = 0; r < R_RANK; r++) acc[r] = 0.f;

    for (int f = tid * 4; f < F_DIM; f += 1024) {
        uint2 hp = *(const uint2*)(h + f);
        float2 f0 = __half22float2(*(__half2*)&hp.x);
        float2 f1 = __half22float2(*(__half2*)&hp.y);
#pragma unroll
        for (int r = 0; r < R_RANK; r++) {
            float4 av = *(const float4*)(a2 + (size_t)r * F_DIM + f);
            acc[r] += f0.x * av.x + f0.y * av.y + f1.x * av.z + f1.y * av.w;
        }
    }
    __shared__ float red[R_RANK][8];
#pragma unroll
    for (int r = 0; r < R_RANK; r++) {
        float v = acc[r];
        for (int o = 16; o > 0; o >>= 1) v += __shfl_down_sync(0xffffffffu, v, o);
        if ((tid & 31) == 0) red[r][tid >> 5] = v;
    }
    __syncthreads();
    if (tid < R_RANK) {
        float v = 0.f;
#pragma unroll
        for (int w = 0; w < 8; w++) v += red[tid][w];
        z2s[n * 16 + k * 8 + tid] = v * SCALING * ew[2 * n + k];
    }
}

// ============================================================================
// fc2 hybrid kernel
// ============================================================================
__device__ void fc2_simt(int bm, int bn, char* smem_u,
    const float* __restrict__ B, const float* __restrict__ b2,
    const float* __restrict__ B2, float* __restrict__ out)
{
    const int K = F_DIM;
    int tid = threadIdx.x;
    float* As = (float*)smem_u;
    float* Bs = As + 16 * 132;
    float acc[TM][TN];
#pragma unroll
    for (int i = 0; i < TM; i++)
#pragma unroll
        for (int j = 0; j < TN; j++) acc[i][j] = 0.f;

    int tx = tid % 16, ty = tid / 16;
    const float* Ab = g_buf + (size_t)bm * BM * K;
    const float* Bb = B + (size_t)bn * BN * K;
    int rowL = tid >> 2;
    int colL = (tid & 3) * 4;

    for (int k0 = 0; k0 < K; k0 += BK) {
#pragma unroll
        for (int i = 0; i < 2; i++) {
            float4 a = *(const float4*)(Ab + (size_t)(rowL + i * 64) * K + k0 + colL);
            As[(colL + 0) * 132 + rowL + i * 64] = a.x;
            As[(colL + 1) * 132 + rowL + i * 64] = a.y;
            As[(colL + 2) * 132 + rowL + i * 64] = a.z;
            As[(colL + 3) * 132 + rowL + i * 64] = a.w;
            float4 b = *(const float4*)(Bb + (size_t)(rowL + i * 64) * K + k0 + colL);
            Bs[(colL + 0) * 132 + rowL + i * 64] = b.x;
            Bs[(colL + 1) * 132 + rowL + i * 64] = b.y;
            Bs[(colL + 2) * 132 + rowL + i * 64] = b.z;
            Bs[(colL + 3) * 132 + rowL + i * 64] = b.w;
        }
        __syncthreads();
#pragma unroll
        for (int kk = 0; kk < BK; kk++) {
            float4 a0 = *(const float4*)&As[kk * 132 + ty * TM];
            float4 a1 = *(const float4*)&As[kk * 132 + ty * TM + 4];
            float4 b0 = *(const float4*)&Bs[kk * 132 + tx * TN];
            float4 b1v = *(const float4*)&Bs[kk * 132 + tx * TN + 4];
            float ra[8] = {a0.x, a0.y, a0.z, a0.w, a1.x, a1.y, a1.z, a1.w};
            float rb[8] = {b0.x, b0.y, b0.z, b0.w, b1v.x, b1v.y, b1v.z, b1v.w};
#pragma unroll
            for (int i = 0; i < TM; i++)
#pragma unroll
                for (int j = 0; j < TN; j++) acc[i][j] += ra[i] * rb[j];
        }
        __syncthreads();
    }

    int nrow0 = bm * BM + ty * TM;
    int dcol0 = bn * BN + tx * TN;
#pragma unroll
    for (int i = 0; i < TM; i++) {
        int n = nrow0 + i;
        float ws = wsum_buf[n];
        int e0 = eidx[2 * n], e1 = eidx[2 * n + 1];
        const float4* zp = (const float4*)&z2s[n * 16];
        float4 z0a = zp[0], z0b = zp[1], z1a = zp[2], z1b = zp[3];
        float ov[TN];
#pragma unroll
        for (int j = 0; j < TN; j++) {
            int d = dcol0 + j;
            float c = acc[i][j] + ws * b2[d];
            const float4* q0 = (const float4*)&B2[((size_t)e0 * D_DIM + d) * R_RANK];
            float4 u0 = q0[0], u1 = q0[1];
            c += z0a.x * u0.x + z0a.y * u0.y + z0a.z * u0.z + z0a.w * u0.w
               + z0b.x * u1.x + z0b.y * u1.y + z0b.z * u1.z + z0b.w * u1.w;
            const float4* q1 = (const float4*)&B2[((size_t)e1 * D_DIM + d) * R_RANK];
            float4 v0 = q1[0], v1 = q1[1];
            c += z1a.x * v0.x + z1a.y * v0.y + z1a.z * v0.z + z1a.w * v0.w
               + z1b.x * v1.x + z1b.y * v1.y + z1b.z * v1.z + z1b.w * v1.w;
            ov[j] = c;
        }
        size_t off = (size_t)n * D_DIM + dcol0;
        *(float4*)&out[off]     = make_float4(ov[0], ov[1], ov[2], ov[3]);
        *(float4*)&out[off + 4] = make_float4(ov[4], ov[5], ov[6], ov[7]);
    }
}

__device__ void fc2_tens(int bm, int bn, char* smem_u,
    const float* __restrict__ W2, const float* __restrict__ b2,
    const float* __restrict__ B2, float* __restrict__ out)
{
    __half* smh = (__half*)smem_u;
    int tid = threadIdx.x, wid = tid >> 5, wr = wid & 3, wc = wid >> 2;
    HC acc[2][4];
    gemm16cv(acc, g_buf + (size_t)bm*128*F_DIM, W2 + (size_t)bn*128*F_DIM, F_DIM, smh);

    float* Cs = (float*)smem_u;
    for (int r = 0; r < 2; r++){
        __syncthreads();
        if ((wr >> 1) == r){
            int rl = (wr & 1) * 32;
#pragma unroll
            for (int i = 0; i < 2; i++)
#pragma unroll
            for (int j = 0; j < 4; j++)
                wmma::store_matrix_sync(Cs + (size_t)(rl+i*16)*136 + wc*64 + j*16,
                                        acc[i][j], 136, wmma::mem_row_major);
        }
        __syncthreads();

        int row_l = tid >> 2;
        int n = bm*128 + r*64 + row_l;
        int c0 = (tid & 3) * 32;
        float ws = wsum_buf[n];
        int e0 = eidx[2*n], e1 = eidx[2*n+1];
        float z0[8], z1[8];
#pragma unroll
        for (int q = 0; q < 8; q++){ z0[q] = z2s[n*16+q]; z1[q] = z2s[n*16+8+q]; }
        const float* crow = &Cs[(size_t)row_l*136];
        for (int jj = 0; jj < 32; jj++){
            int col = c0 + jj;
            int d = bn*128 + col;
            float c = crow[col] + ws*b2[d];
            const float4* q0 = (const float4*)&B2[((size_t)e0*D_DIM + d)*R_RANK];
            const float4* q1 = (const float4*)&B2[((size_t)e1*D_DIM + d)*R_RANK];
            float4 u0=q0[0], u1=q0[1], v0=q1[0], v1=q1[1];
            c += z0[0]*u0.x + z0[1]*u0.y + z0[2]*u0.z + z0[3]*u0.w
               + z0[4]*u1.x + z0[5]*u1.y + z0[6]*u1.z + z0[7]*u1.w;
            c += z1[0]*v0.x + z1[1]*v0.y + z1[2]*v0.z + z1[3]*v0.w
               + z1[4]*v1.x + z1[5]*v1.y + z1[6]*v1.z + z1[7]*v1.w;
            out[(size_t)n*D_DIM + d] = c;
        }
    }
}

__global__ __launch_bounds__(256, 2) void fc2_hyb(
    const float* __restrict__ W2, const float* __restrict__ b2,
    const float* __restrict__ B2, float* __restrict__ out)
{
    __shared__ __align__(16) char smem_u[36864];
    int b = blockIdx.x, slot = b & 15, grp = b >> 4;   // grp in [0,32)
    if (slot < 5){
        int i = grp * 5 + slot;          // [0,160) = 10 x 16
        fc2_simt(i / 16, i % 16, smem_u, W2, b2, B2, out);
    } else {
        int j = grp * 11 + (slot - 5);   // [0,352) = 22 x 16
        fc2_tens(TSPLIT + j / 16, j % 16, smem_u, W2, b2, B2, out);
    }
}

// ------------------------- launch ------------------------------------------
extern "C" void kernel_launch(void* const* d_in, const int* in_sizes, int n_in,
                              void* d_out, int out_size)
{
    (void)in_sizes; (void)n_in; (void)out_size;
    const float* x  = (const float*)d_in[0];
    const float* Wr = (const float*)d_in[1];
    const float* br = (const float*)d_in[2];
    const float* W1 = (const float*)d_in[3];
    const float* b1 = (const float*)d_in[4];
    const float* W2 = (const float*)d_in[5];
    const float* b2 = (const float*)d_in[6];
    const float* A1 = (const float*)d_in[7];
    const float* B1 = (const float*)d_in[8];
    const float* A2 = (const float*)d_in[9];
    const float* B2 = (const float*)d_in[10];
    float* out = (float*)d_out;

    router_kernel<<<N_TOK, 256>>>(x, Wr, br, A1);
    fc1_hyb<<<2048, 256>>>(x, W1, b1, B1);
    z2_kernel<<<dim3(N_TOK, 2), 256>>>(A2);
    fc2_hyb<<<512, 256>>>(W2, b2, B2, out);
}